// round 6
// baseline (speedup 1.0000x reference)
#include <cuda_runtime.h>
#include <math.h>

// ---------------------------------------------------------------------------
// B=8, Nc=1024, Nt=1024, Dx=3, Dy=32, H=128
// inputs: xc, yc, xt, W0, b0, W1, b1, W2, b2, W3, b3 (all f32)
// out: (B, Nt, 32) f32
// ---------------------------------------------------------------------------

#define B_SZ 8
#define NC 1024
#define NT 1024

typedef unsigned long long ull;

// q[0..2]=2*sig*xt*L2E, q[3..5]=-sig*L2E, q[6]=-(sum sig*xt^2)*L2E
__device__ float g_q[B_SZ * NT * 8];

// ---------------- packed f32x2 helpers (Blackwell FFMA2) -------------------
__device__ __forceinline__ ull dup2(float x) {
    ull r; asm("mov.b64 %0, {%1, %1};" : "=l"(r) : "f"(x)); return r;
}
__device__ __forceinline__ void fma2(ull& d, ull a, ull b) {
    asm("fma.rn.f32x2 %0, %1, %2, %0;" : "+l"(d) : "l"(a), "l"(b));
}
__device__ __forceinline__ ull mul2(ull a, ull b) {
    ull r; asm("mul.rn.f32x2 %0, %1, %2;" : "=l"(r) : "l"(a), "l"(b)); return r;
}
__device__ __forceinline__ ull add2(ull a, ull b) {
    ull r; asm("add.rn.f32x2 %0, %1, %2;" : "=l"(r) : "l"(a), "l"(b)); return r;
}
__device__ __forceinline__ void unpack2(ull v, float& lo, float& hi) {
    asm("mov.b64 {%0, %1}, %2;" : "=f"(lo), "=f"(hi) : "l"(v));
}
__device__ __forceinline__ float ex2f(float x) {
    float y; asm("ex2.approx.ftz.f32 %0, %1;" : "=f"(y) : "f"(x)); return y;
}

// ======================= Kernel 1: MLP -> sigma -> q =======================
// 256 blocks x 256 threads, 32 points/block, 2 blocks/SM.
// Thread owns units (j, j+64) for 8 points of group g: 8 FFMA2 per k-step
// against 4 crossbar cycles (balanced).

#define TPB1 256
#define oW   0        /* 16384: W1 then W2 */
#define ohA  16384    /* 128 rows x 36 = 4608 */
#define ohB  20992    /* 4608 */
#define oW0  25600    /* 384 */
#define oW3  25984    /* 384 */
#define ob0  26368    /* 128 */
#define ob1  26496
#define ob2  26624
#define ob3  26752    /* 16 */
#define oxt  26768    /* 96 -> 112 */
#define oso  26880    /* 128 */
#define SMEM1_FLOATS 27008

__device__ __forceinline__ void cp4(float* dst, const float* src, int n4, int tid) {
    const float4* s4 = (const float4*)src;
    float4* d4 = (float4*)dst;
    for (int i = tid; i < n4; i += TPB1) d4[i] = s4[i];
}

__device__ __forceinline__ void hidden_layer(float* S, int oin, int oout,
                                             int ob, int g, int j) {
    ull A0, A1, A2, A3, A4, A5, A6, A7;
    A0 = A1 = A2 = A3 = dup2(S[ob + j]);
    A4 = A5 = A6 = A7 = dup2(S[ob + j + 64]);
#pragma unroll 8
    for (int k = 0; k < 128; ++k) {
        const float* ap = &S[oin + k * 36 + g * 8];
        ulonglong2 p01 = *(const ulonglong2*)ap;
        ulonglong2 p23 = *(const ulonglong2*)(ap + 4);
        ull wa = dup2(S[oW + k * 128 + j]);
        ull wb = dup2(S[oW + k * 128 + j + 64]);
        fma2(A0, p01.x, wa); fma2(A1, p01.y, wa);
        fma2(A2, p23.x, wa); fma2(A3, p23.y, wa);
        fma2(A4, p01.x, wb); fma2(A5, p01.y, wb);
        fma2(A6, p23.x, wb); fma2(A7, p23.y, wb);
    }
    float v[16];
    unpack2(A0, v[0], v[1]);   unpack2(A1, v[2], v[3]);
    unpack2(A2, v[4], v[5]);   unpack2(A3, v[6], v[7]);
    unpack2(A4, v[8], v[9]);   unpack2(A5, v[10], v[11]);
    unpack2(A6, v[12], v[13]); unpack2(A7, v[14], v[15]);
    float4* r0 = (float4*)&S[oout + j * 36 + g * 8];
    r0[0] = make_float4(fmaxf(v[0], 0.f), fmaxf(v[1], 0.f), fmaxf(v[2], 0.f), fmaxf(v[3], 0.f));
    r0[1] = make_float4(fmaxf(v[4], 0.f), fmaxf(v[5], 0.f), fmaxf(v[6], 0.f), fmaxf(v[7], 0.f));
    float4* r1 = (float4*)&S[oout + (j + 64) * 36 + g * 8];
    r1[0] = make_float4(fmaxf(v[8], 0.f), fmaxf(v[9], 0.f), fmaxf(v[10], 0.f), fmaxf(v[11], 0.f));
    r1[1] = make_float4(fmaxf(v[12], 0.f), fmaxf(v[13], 0.f), fmaxf(v[14], 0.f), fmaxf(v[15], 0.f));
}

__global__ void __launch_bounds__(TPB1, 2)
mlp_kernel(const float* __restrict__ xt,
           const float* __restrict__ W0, const float* __restrict__ b0,
           const float* __restrict__ W1, const float* __restrict__ b1,
           const float* __restrict__ W2, const float* __restrict__ b2,
           const float* __restrict__ W3, const float* __restrict__ b3) {
    extern __shared__ float S[];
    int tid = threadIdx.x;
    int wid = tid >> 5, lane = tid & 31;
    int g = tid >> 6;   // 4 groups x 8 points
    int j = tid & 63;   // units j, j+64

    cp4(&S[oW], W1, 4096, tid);
    cp4(&S[oW0], W0, 96, tid);
    cp4(&S[oW3], W3, 96, tid);
    cp4(&S[ob0], b0, 32, tid);
    cp4(&S[ob1], b1, 32, tid);
    cp4(&S[ob2], b2, 32, tid);
    if (tid < 3) S[ob3 + tid] = b3[tid];

    int pbase = blockIdx.x * 32;
    if (tid < 96) S[oxt + tid] = xt[pbase * 3 + tid];
    __syncthreads();

    // layer 0: 3 -> 128
    {
        float bb0 = S[ob0 + j], bb1 = S[ob0 + j + 64];
        float w00 = S[oW0 + j],       w01 = S[oW0 + j + 64];
        float w10 = S[oW0 + 128 + j], w11 = S[oW0 + 128 + j + 64];
        float w20 = S[oW0 + 256 + j], w21 = S[oW0 + 256 + j + 64];
        float a0[8], a1[8];
#pragma unroll
        for (int p = 0; p < 8; ++p) {
            int lp = g * 8 + p;
            float x0 = S[oxt + lp * 3 + 0];
            float x1 = S[oxt + lp * 3 + 1];
            float x2 = S[oxt + lp * 3 + 2];
            a0[p] = fmaxf(fmaf(x2, w20, fmaf(x1, w10, fmaf(x0, w00, bb0))), 0.f);
            a1[p] = fmaxf(fmaf(x2, w21, fmaf(x1, w11, fmaf(x0, w01, bb1))), 0.f);
        }
        float4* r0 = (float4*)&S[ohA + j * 36 + g * 8];
        r0[0] = make_float4(a0[0], a0[1], a0[2], a0[3]);
        r0[1] = make_float4(a0[4], a0[5], a0[6], a0[7]);
        float4* r1 = (float4*)&S[ohA + (j + 64) * 36 + g * 8];
        r1[0] = make_float4(a1[0], a1[1], a1[2], a1[3]);
        r1[1] = make_float4(a1[4], a1[5], a1[6], a1[7]);
    }
    __syncthreads();

    hidden_layer(S, ohA, ohB, ob1, g, j);   // layer 1 (W1)
    __syncthreads();
    cp4(&S[oW], W2, 4096, tid);             // reload with W2 (L2-hot)
    __syncthreads();
    hidden_layer(S, ohB, ohA, ob2, g, j);   // layer 2 (W2)
    __syncthreads();

    // output layer 128 -> 3: warps 0..2, d = wid, lane = point
    if (wid < 3) {
        int d = wid;
        float a0 = 0.f, a1 = 0.f, a2 = 0.f, a3 = 0.f;
#pragma unroll 4
        for (int k = 0; k < 128; k += 4) {
            a0 = fmaf(S[ohA + (k + 0) * 36 + lane], S[oW3 + (k + 0) * 3 + d], a0);
            a1 = fmaf(S[ohA + (k + 1) * 36 + lane], S[oW3 + (k + 1) * 3 + d], a1);
            a2 = fmaf(S[ohA + (k + 2) * 36 + lane], S[oW3 + (k + 2) * 3 + d], a2);
            a3 = fmaf(S[ohA + (k + 3) * 36 + lane], S[oW3 + (k + 3) * 3 + d], a3);
        }
        S[oso + lane * 4 + d] = S[ob3 + d] + ((a0 + a1) + (a2 + a3));
    }
    __syncthreads();

    // epilogue: sigma = exp(o), build q (log2 domain)
    if (tid < 32) {
        float o0 = S[oso + tid * 4 + 0];
        float o1 = S[oso + tid * 4 + 1];
        float o2 = S[oso + tid * 4 + 2];
        float s0 = expf(o0), s1 = expf(o1), s2 = expf(o2);
        float x0 = S[oxt + tid * 3 + 0];
        float x1 = S[oxt + tid * 3 + 1];
        float x2 = S[oxt + tid * 3 + 2];
        const float L2E = 1.44269504088896340736f;
        float c6 = -(s0 * x0 * x0 + s1 * x1 * x1 + s2 * x2 * x2) * L2E;
        float4* qd = (float4*)&g_q[(pbase + tid) * 8];
        qd[0] = make_float4(2.f * s0 * x0 * L2E, 2.f * s1 * x1 * L2E,
                            2.f * s2 * x2 * L2E, -s0 * L2E);
        qd[1] = make_float4(-s1 * L2E, -s2 * L2E, c6, 0.f);
    }
}

// ======================= Kernel 2: streaming softmax-attention =============
// grid (64, 8) = 512 blocks x 128 threads; 16 targets/block; 128-ctx chunks.
// Small blocks -> cheap barriers + ~5 blocks/SM for latency hiding.

#define AKV  0       /* 6 x 128 key features */
#define ASYC 768     /* 128 x 32 values */
#define ASW  4864    /* 16 targets x 132 weights (t-major) */
#define ASQ  6976    /* 16 x 8 queries */
#define ASSC 7104    /* 16 */
#define ASL  7120    /* 16 */
#define ARED 0       /* 4 x 16 x 32 = 2048, overlays AKV/ASYC after loop */
#define ATOT 7136

__global__ void __launch_bounds__(128, 5)
attn_kernel(const float* __restrict__ xc, const float* __restrict__ yc,
            float* __restrict__ out) {
    __shared__ __align__(16) float S[ATOT];

    int tid = threadIdx.x;
    int wid = tid >> 5, lane = tid & 31;
    int b = blockIdx.y;
    int t0 = blockIdx.x * 16;

    S[ASQ + tid] = g_q[(b * NT + t0) * 8 + tid];
    __syncthreads();

    // softmax mapping: warp owns targets wid*4+tsub; csub = context subset
    int tsub = lane >> 3, csub = lane & 7;
    int tq = wid * 4 + tsub;
    ull q0d = dup2(S[ASQ + tq * 8 + 0]);
    ull q1d = dup2(S[ASQ + tq * 8 + 1]);
    ull q2d = dup2(S[ASQ + tq * 8 + 2]);
    ull q3d = dup2(S[ASQ + tq * 8 + 3]);
    ull q4d = dup2(S[ASQ + tq * 8 + 4]);
    ull q5d = dup2(S[ASQ + tq * 8 + 5]);
    ull q6d = dup2(S[ASQ + tq * 8 + 6]);
    float mrun = -1e30f, lrun = 0.f;

    // GEMM mapping: warp = 32-context split; thread: targets {tg, tg+8},
    // dy dims dg*8 .. dg*8+8
    int tg = lane >> 2, dg = lane & 3;

    ull acc[2][4];
#pragma unroll
    for (int i = 0; i < 2; ++i)
#pragma unroll
        for (int d2 = 0; d2 < 4; ++d2) acc[i][d2] = 0ull;

    for (int ch = 0; ch < 8; ++ch) {
        int cbase = ch * 128;
        __syncthreads();   // prior chunk consumers done

        {   // key features (SoA), tid == context index
            const float* xp = &xc[(b * NC + cbase + tid) * 3];
            float x0 = xp[0], x1 = xp[1], x2 = xp[2];
            S[AKV + tid] = x0;
            S[AKV + 128 + tid] = x1;
            S[AKV + 256 + tid] = x2;
            S[AKV + 384 + tid] = x0 * x0;
            S[AKV + 512 + tid] = x1 * x1;
            S[AKV + 640 + tid] = x2 * x2;
        }
        {   // value tile
            const float4* ys = (const float4*)&yc[(b * NC + cbase) * 32];
            float4* yd = (float4*)&S[ASYC];
#pragma unroll
            for (int r = 0; r < 8; ++r) yd[tid + 128 * r] = ys[tid + 128 * r];
        }
        __syncthreads();

        // ---- logits: 16 contexts per lane ----
        float preg[16];
        float lmax = -1e30f;
#pragma unroll
        for (int i4 = 0; i4 < 4; ++i4) {
            int c0 = csub * 16 + i4 * 4;
            ulonglong2 f0 = *(const ulonglong2*)&S[AKV + c0];
            ulonglong2 f1 = *(const ulonglong2*)&S[AKV + 128 + c0];
            ulonglong2 f2 = *(const ulonglong2*)&S[AKV + 256 + c0];
            ulonglong2 f3 = *(const ulonglong2*)&S[AKV + 384 + c0];
            ulonglong2 f4 = *(const ulonglong2*)&S[AKV + 512 + c0];
            ulonglong2 f5 = *(const ulonglong2*)&S[AKV + 640 + c0];
            ull P01 = q6d, P23 = q6d;
            fma2(P01, f0.x, q0d); fma2(P23, f0.y, q0d);
            fma2(P01, f1.x, q1d); fma2(P23, f1.y, q1d);
            fma2(P01, f2.x, q2d); fma2(P23, f2.y, q2d);
            fma2(P01, f3.x, q3d); fma2(P23, f3.y, q3d);
            fma2(P01, f4.x, q4d); fma2(P23, f4.y, q4d);
            fma2(P01, f5.x, q5d); fma2(P23, f5.y, q5d);
            unpack2(P01, preg[i4 * 4 + 0], preg[i4 * 4 + 1]);
            unpack2(P23, preg[i4 * 4 + 2], preg[i4 * 4 + 3]);
            lmax = fmaxf(lmax, fmaxf(fmaxf(preg[i4 * 4], preg[i4 * 4 + 1]),
                                     fmaxf(preg[i4 * 4 + 2], preg[i4 * 4 + 3])));
        }
        lmax = fmaxf(lmax, __shfl_xor_sync(0xffffffffu, lmax, 1));
        lmax = fmaxf(lmax, __shfl_xor_sync(0xffffffffu, lmax, 2));
        lmax = fmaxf(lmax, __shfl_xor_sync(0xffffffffu, lmax, 4));
        float mn = fmaxf(mrun, lmax);
        float scl = ex2f(mrun - mn);
        mrun = mn;

        float lsum = 0.f;
#pragma unroll
        for (int i = 0; i < 16; ++i) {
            preg[i] = ex2f(preg[i] - mn);
            lsum += preg[i];
        }
        lsum += __shfl_xor_sync(0xffffffffu, lsum, 1);
        lsum += __shfl_xor_sync(0xffffffffu, lsum, 2);
        lsum += __shfl_xor_sync(0xffffffffu, lsum, 4);
        lrun = fmaf(lrun, scl, lsum);

        {   // store weights t-major (stride 132)
            float4* wd = (float4*)&S[ASW + tq * 132 + csub * 16];
            wd[0] = make_float4(preg[0], preg[1], preg[2], preg[3]);
            wd[1] = make_float4(preg[4], preg[5], preg[6], preg[7]);
            wd[2] = make_float4(preg[8], preg[9], preg[10], preg[11]);
            wd[3] = make_float4(preg[12], preg[13], preg[14], preg[15]);
        }
        if (csub == 0) S[ASSC + tq] = scl;
        __syncthreads();

        // ---- rescale accumulators ----
#pragma unroll
        for (int i = 0; i < 2; ++i) {
            ull sc = dup2(S[ASSC + tg + 8 * i]);
#pragma unroll
            for (int d2 = 0; d2 < 4; ++d2) acc[i][d2] = mul2(acc[i][d2], sc);
        }

        // ---- value GEMM: warp covers contexts wid*32 .. wid*32+32 ----
#pragma unroll
        for (int k4 = 0; k4 < 8; ++k4) {
            int c0 = wid * 32 + k4 * 4;
            float4 wv0 = *(const float4*)&S[ASW + (tg    ) * 132 + c0];
            float4 wv1 = *(const float4*)&S[ASW + (tg + 8) * 132 + c0];
#define DO_CI(CI, COMP)                                                        \
            {                                                                  \
                const float* yp = &S[ASYC + (c0 + CI) * 32 + dg * 8];          \
                ulonglong2 ya = *(const ulonglong2*)yp;                        \
                ulonglong2 yb = *(const ulonglong2*)(yp + 4);                  \
                ull w;                                                         \
                w = dup2(wv0.COMP);                                            \
                fma2(acc[0][0], ya.x, w); fma2(acc[0][1], ya.y, w);            \
                fma2(acc[0][2], yb.x, w); fma2(acc[0][3], yb.y, w);            \
                w = dup2(wv1.COMP);                                            \
                fma2(acc[1][0], ya.x, w); fma2(acc[1][1], ya.y, w);            \
                fma2(acc[1][2], yb.x, w); fma2(acc[1][3], yb.y, w);            \
            }
            DO_CI(0, x) DO_CI(1, y) DO_CI(2, z) DO_CI(3, w)
#undef DO_CI
        }
    }
    __syncthreads();   // weights/values dead; reuse as reduce buffers

    if (csub == 0) S[ASL + tq] = lrun;

    // each warp stores its c-split partials
#pragma unroll
    for (int i = 0; i < 2; ++i) {
        int t = tg + 8 * i;
        ulonglong2* dst = (ulonglong2*)&S[ARED + wid * 512 + t * 32 + dg * 8];
        ulonglong2 v0, v1;
        v0.x = acc[i][0]; v0.y = acc[i][1];
        v1.x = acc[i][2]; v1.y = acc[i][3];
        dst[0] = v0; dst[1] = v1;
    }
    __syncthreads();

    // final: sum 4 warp-buffers, normalize, store
    {
        int t = tid >> 3, d8 = tid & 7;
        ull r0 = 0ull, r1 = 0ull;
#pragma unroll
        for (int sI = 0; sI < 4; ++sI) {
            ulonglong2 v = *(const ulonglong2*)&S[ARED + sI * 512 + t * 32 + d8 * 4];
            r0 = add2(r0, v.x);
            r1 = add2(r1, v.y);
        }
        ull inv = dup2(1.0f / S[ASL + t]);
        r0 = mul2(r0, inv);
        r1 = mul2(r1, inv);
        ulonglong2 o; o.x = r0; o.y = r1;
        *(ulonglong2*)&out[(b * NT + t0 + t) * 32 + d8 * 4] = o;
    }
}

// ============================== launch =====================================
extern "C" void kernel_launch(void* const* d_in, const int* in_sizes, int n_in,
                              void* d_out, int out_size) {
    (void)in_sizes; (void)n_in; (void)out_size;
    const float* xc = (const float*)d_in[0];
    const float* yc = (const float*)d_in[1];
    const float* xt = (const float*)d_in[2];
    const float* W0 = (const float*)d_in[3];
    const float* b0 = (const float*)d_in[4];
    const float* W1 = (const float*)d_in[5];
    const float* b1 = (const float*)d_in[6];
    const float* W2 = (const float*)d_in[7];
    const float* b2 = (const float*)d_in[8];
    const float* W3 = (const float*)d_in[9];
    const float* b3 = (const float*)d_in[10];
    float* out = (float*)d_out;

    size_t smem1 = SMEM1_FLOATS * sizeof(float);
    cudaFuncSetAttribute(mlp_kernel, cudaFuncAttributeMaxDynamicSharedMemorySize,
                         (int)smem1);

    mlp_kernel<<<256, TPB1, smem1>>>(xt, W0, b0, W1, b1, W2, b2, W3, b3);
    attn_kernel<<<dim3(NT / 16, B_SZ), 128>>>(xc, yc, out);
}

// round 8
// speedup vs baseline: 1.0750x; 1.0750x over previous
#include <cuda_runtime.h>
#include <math.h>

// ---------------------------------------------------------------------------
// B=8, Nc=1024, Nt=1024, Dx=3, Dy=32, H=128
// inputs: xc, yc, xt, W0, b0, W1, b1, W2, b2, W3, b3 (all f32)
// out: (B, Nt, 32) f32
// ---------------------------------------------------------------------------

#define B_SZ 8
#define NC 1024
#define NT 1024

typedef unsigned long long ull;

// q[0..2]=2*sig*xt*L2E, q[3..5]=-sig*L2E, q[6]=-(sum sig*xt^2)*L2E
__device__ float g_q[B_SZ * NT * 8];
// context-split partials: z in {0,1}
__device__ float g_pacc[2 * B_SZ * NT * 32];   // unnormalized weighted sums
__device__ float g_pm[2 * B_SZ * NT];          // running max (log2 domain)
__device__ float g_pl[2 * B_SZ * NT];          // running sum

// ---------------- packed f32x2 helpers (Blackwell FFMA2) -------------------
__device__ __forceinline__ ull dup2(float x) {
    ull r; asm("mov.b64 %0, {%1, %1};" : "=l"(r) : "f"(x)); return r;
}
__device__ __forceinline__ void fma2(ull& d, ull a, ull b) {
    asm("fma.rn.f32x2 %0, %1, %2, %0;" : "+l"(d) : "l"(a), "l"(b));
}
__device__ __forceinline__ ull mul2(ull a, ull b) {
    ull r; asm("mul.rn.f32x2 %0, %1, %2;" : "=l"(r) : "l"(a), "l"(b)); return r;
}
__device__ __forceinline__ ull add2(ull a, ull b) {
    ull r; asm("add.rn.f32x2 %0, %1, %2;" : "=l"(r) : "l"(a), "l"(b)); return r;
}
__device__ __forceinline__ void unpack2(ull v, float& lo, float& hi) {
    asm("mov.b64 {%0, %1}, %2;" : "=f"(lo), "=f"(hi) : "l"(v));
}
__device__ __forceinline__ float ex2f(float x) {
    float y; asm("ex2.approx.ftz.f32 %0, %1;" : "=f"(y) : "f"(x)); return y;
}

// ======================= Kernel 1: MLP -> sigma -> q =======================
// (unchanged from R6: 256 blocks x 256 threads, 32 points/block, 2/SM)

#define TPB1 256
#define oW   0        /* 16384: W1 then W2 */
#define ohA  16384    /* 128 x 36 = 4608 */
#define ohB  20992    /* 4608 */
#define oW0  25600
#define oW3  25984
#define ob0  26368
#define ob1  26496
#define ob2  26624
#define ob3  26752
#define oxt  26768
#define oso  26880
#define SMEM1_FLOATS 27008

__device__ __forceinline__ void cp4(float* dst, const float* src, int n4, int tid) {
    const float4* s4 = (const float4*)src;
    float4* d4 = (float4*)dst;
    for (int i = tid; i < n4; i += TPB1) d4[i] = s4[i];
}

__device__ __forceinline__ void hidden_layer(float* S, int oin, int oout,
                                             int ob, int g, int j) {
    ull A0, A1, A2, A3, A4, A5, A6, A7;
    A0 = A1 = A2 = A3 = dup2(S[ob + j]);
    A4 = A5 = A6 = A7 = dup2(S[ob + j + 64]);
#pragma unroll 8
    for (int k = 0; k < 128; ++k) {
        const float* ap = &S[oin + k * 36 + g * 8];
        ulonglong2 p01 = *(const ulonglong2*)ap;
        ulonglong2 p23 = *(const ulonglong2*)(ap + 4);
        ull wa = dup2(S[oW + k * 128 + j]);
        ull wb = dup2(S[oW + k * 128 + j + 64]);
        fma2(A0, p01.x, wa); fma2(A1, p01.y, wa);
        fma2(A2, p23.x, wa); fma2(A3, p23.y, wa);
        fma2(A4, p01.x, wb); fma2(A5, p01.y, wb);
        fma2(A6, p23.x, wb); fma2(A7, p23.y, wb);
    }
    float v[16];
    unpack2(A0, v[0], v[1]);   unpack2(A1, v[2], v[3]);
    unpack2(A2, v[4], v[5]);   unpack2(A3, v[6], v[7]);
    unpack2(A4, v[8], v[9]);   unpack2(A5, v[10], v[11]);
    unpack2(A6, v[12], v[13]); unpack2(A7, v[14], v[15]);
    float4* r0 = (float4*)&S[oout + j * 36 + g * 8];
    r0[0] = make_float4(fmaxf(v[0], 0.f), fmaxf(v[1], 0.f), fmaxf(v[2], 0.f), fmaxf(v[3], 0.f));
    r0[1] = make_float4(fmaxf(v[4], 0.f), fmaxf(v[5], 0.f), fmaxf(v[6], 0.f), fmaxf(v[7], 0.f));
    float4* r1 = (float4*)&S[oout + (j + 64) * 36 + g * 8];
    r1[0] = make_float4(fmaxf(v[8], 0.f), fmaxf(v[9], 0.f), fmaxf(v[10], 0.f), fmaxf(v[11], 0.f));
    r1[1] = make_float4(fmaxf(v[12], 0.f), fmaxf(v[13], 0.f), fmaxf(v[14], 0.f), fmaxf(v[15], 0.f));
}

__global__ void __launch_bounds__(TPB1, 2)
mlp_kernel(const float* __restrict__ xt,
           const float* __restrict__ W0, const float* __restrict__ b0,
           const float* __restrict__ W1, const float* __restrict__ b1,
           const float* __restrict__ W2, const float* __restrict__ b2,
           const float* __restrict__ W3, const float* __restrict__ b3) {
    extern __shared__ float S[];
    int tid = threadIdx.x;
    int wid = tid >> 5, lane = tid & 31;
    int g = tid >> 6;
    int j = tid & 63;

    cp4(&S[oW], W1, 4096, tid);
    cp4(&S[oW0], W0, 96, tid);
    cp4(&S[oW3], W3, 96, tid);
    cp4(&S[ob0], b0, 32, tid);
    cp4(&S[ob1], b1, 32, tid);
    cp4(&S[ob2], b2, 32, tid);
    if (tid < 3) S[ob3 + tid] = b3[tid];

    int pbase = blockIdx.x * 32;
    if (tid < 96) S[oxt + tid] = xt[pbase * 3 + tid];
    __syncthreads();

    {   // layer 0: 3 -> 128
        float bb0 = S[ob0 + j], bb1 = S[ob0 + j + 64];
        float w00 = S[oW0 + j],       w01 = S[oW0 + j + 64];
        float w10 = S[oW0 + 128 + j], w11 = S[oW0 + 128 + j + 64];
        float w20 = S[oW0 + 256 + j], w21 = S[oW0 + 256 + j + 64];
        float a0[8], a1[8];
#pragma unroll
        for (int p = 0; p < 8; ++p) {
            int lp = g * 8 + p;
            float x0 = S[oxt + lp * 3 + 0];
            float x1 = S[oxt + lp * 3 + 1];
            float x2 = S[oxt + lp * 3 + 2];
            a0[p] = fmaxf(fmaf(x2, w20, fmaf(x1, w10, fmaf(x0, w00, bb0))), 0.f);
            a1[p] = fmaxf(fmaf(x2, w21, fmaf(x1, w11, fmaf(x0, w01, bb1))), 0.f);
        }
        float4* r0 = (float4*)&S[ohA + j * 36 + g * 8];
        r0[0] = make_float4(a0[0], a0[1], a0[2], a0[3]);
        r0[1] = make_float4(a0[4], a0[5], a0[6], a0[7]);
        float4* r1 = (float4*)&S[ohA + (j + 64) * 36 + g * 8];
        r1[0] = make_float4(a1[0], a1[1], a1[2], a1[3]);
        r1[1] = make_float4(a1[4], a1[5], a1[6], a1[7]);
    }
    __syncthreads();

    hidden_layer(S, ohA, ohB, ob1, g, j);
    __syncthreads();
    cp4(&S[oW], W2, 4096, tid);
    __syncthreads();
    hidden_layer(S, ohB, ohA, ob2, g, j);
    __syncthreads();

    if (wid < 3) {    // output layer 128 -> 3
        int d = wid;
        float a0 = 0.f, a1 = 0.f, a2 = 0.f, a3 = 0.f;
#pragma unroll 4
        for (int k = 0; k < 128; k += 4) {
            a0 = fmaf(S[ohA + (k + 0) * 36 + lane], S[oW3 + (k + 0) * 3 + d], a0);
            a1 = fmaf(S[ohA + (k + 1) * 36 + lane], S[oW3 + (k + 1) * 3 + d], a1);
            a2 = fmaf(S[ohA + (k + 2) * 36 + lane], S[oW3 + (k + 2) * 3 + d], a2);
            a3 = fmaf(S[ohA + (k + 3) * 36 + lane], S[oW3 + (k + 3) * 3 + d], a3);
        }
        S[oso + lane * 4 + d] = S[ob3 + d] + ((a0 + a1) + (a2 + a3));
    }
    __syncthreads();

    if (tid < 32) {   // epilogue
        float o0 = S[oso + tid * 4 + 0];
        float o1 = S[oso + tid * 4 + 1];
        float o2 = S[oso + tid * 4 + 2];
        float s0 = expf(o0), s1 = expf(o1), s2 = expf(o2);
        float x0 = S[oxt + tid * 3 + 0];
        float x1 = S[oxt + tid * 3 + 1];
        float x2 = S[oxt + tid * 3 + 2];
        const float L2E = 1.44269504088896340736f;
        float c6 = -(s0 * x0 * x0 + s1 * x1 * x1 + s2 * x2 * x2) * L2E;
        float4* qd = (float4*)&g_q[(pbase + tid) * 8];
        qd[0] = make_float4(2.f * s0 * x0 * L2E, 2.f * s1 * x1 * L2E,
                            2.f * s2 * x2 * L2E, -s0 * L2E);
        qd[1] = make_float4(-s1 * L2E, -s2 * L2E, c6, 0.f);
    }
}

// ======================= Kernel 2: attention partials ======================
// grid (32, 8, 2) = 512 blocks x 256 threads. 32 targets, 512 contexts/block
// (z = context half). 3 blocks/SM. Emits unnormalized partials + (m, l).

#define AKV  0       /* 6 x 128 key features */
#define ASYC 768     /* 128 x 32 values */
#define ASW  4864    /* 32 x 132 weights, t-major */
#define ASQ  9088    /* 32 x 8 queries */
#define ASSC 9344    /* 32 rescale */
#define ARED 0       /* 4 x 1024 reduce (overlays AKV/ASYC) */
#define ATOT 9376

__global__ void __launch_bounds__(256, 3)
attn_kernel(const float* __restrict__ xc, const float* __restrict__ yc) {
    __shared__ __align__(16) float S[ATOT];

    int tid = threadIdx.x;
    int wid = tid >> 5, lane = tid & 31;
    int b = blockIdx.y;
    int t0 = blockIdx.x * 32;
    int z = blockIdx.z;

    S[ASQ + tid] = g_q[(b * NT + t0) * 8 + tid];
    __syncthreads();

    // softmax mapping: warp owns targets wid*4+tsub; csub = ctx subset
    int tsub = lane >> 3, csub = lane & 7;
    int tq = wid * 4 + tsub;
    ull q0d = dup2(S[ASQ + tq * 8 + 0]);
    ull q1d = dup2(S[ASQ + tq * 8 + 1]);
    ull q2d = dup2(S[ASQ + tq * 8 + 2]);
    ull q3d = dup2(S[ASQ + tq * 8 + 3]);
    ull q4d = dup2(S[ASQ + tq * 8 + 4]);
    ull q5d = dup2(S[ASQ + tq * 8 + 5]);
    ull q6d = dup2(S[ASQ + tq * 8 + 6]);
    float mrun = -1e30f, lrun = 0.f;

    // GEMM mapping: warp = 16-context split; thread: targets tg+8i (4),
    // dims dg*8..dg*8+8
    int tg = lane >> 2, dg = lane & 3;

    ull acc[4][4];
#pragma unroll
    for (int i = 0; i < 4; ++i)
#pragma unroll
        for (int d2 = 0; d2 < 4; ++d2) acc[i][d2] = 0ull;

    for (int ch = 0; ch < 4; ++ch) {
        int cbase = z * 512 + ch * 128;
        __syncthreads();   // prior chunk consumers done

        if (tid < 128) {   // key features (SoA)
            const float* xp = &xc[(b * NC + cbase + tid) * 3];
            float x0 = xp[0], x1 = xp[1], x2 = xp[2];
            S[AKV + tid] = x0;
            S[AKV + 128 + tid] = x1;
            S[AKV + 256 + tid] = x2;
            S[AKV + 384 + tid] = x0 * x0;
            S[AKV + 512 + tid] = x1 * x1;
            S[AKV + 640 + tid] = x2 * x2;
        }
        {   // value tile: 1024 float4s over 256 threads
            const float4* ys = (const float4*)&yc[(b * NC + cbase) * 32];
            float4* yd = (float4*)&S[ASYC];
#pragma unroll
            for (int r = 0; r < 4; ++r) yd[tid + 256 * r] = ys[tid + 256 * r];
        }
        __syncthreads();

        // ---- logits: 16 contexts per lane ----
        float preg[16];
        float lmax = -1e30f;
#pragma unroll
        for (int i4 = 0; i4 < 4; ++i4) {
            int c0 = csub * 16 + i4 * 4;
            ulonglong2 f0 = *(const ulonglong2*)&S[AKV + c0];
            ulonglong2 f1 = *(const ulonglong2*)&S[AKV + 128 + c0];
            ulonglong2 f2 = *(const ulonglong2*)&S[AKV + 256 + c0];
            ulonglong2 f3 = *(const ulonglong2*)&S[AKV + 384 + c0];
            ulonglong2 f4 = *(const ulonglong2*)&S[AKV + 512 + c0];
            ulonglong2 f5 = *(const ulonglong2*)&S[AKV + 640 + c0];
            ull P01 = q6d, P23 = q6d;
            fma2(P01, f0.x, q0d); fma2(P23, f0.y, q0d);
            fma2(P01, f1.x, q1d); fma2(P23, f1.y, q1d);
            fma2(P01, f2.x, q2d); fma2(P23, f2.y, q2d);
            fma2(P01, f3.x, q3d); fma2(P23, f3.y, q3d);
            fma2(P01, f4.x, q4d); fma2(P23, f4.y, q4d);
            fma2(P01, f5.x, q5d); fma2(P23, f5.y, q5d);
            unpack2(P01, preg[i4 * 4 + 0], preg[i4 * 4 + 1]);
            unpack2(P23, preg[i4 * 4 + 2], preg[i4 * 4 + 3]);
            lmax = fmaxf(lmax, fmaxf(fmaxf(preg[i4 * 4], preg[i4 * 4 + 1]),
                                     fmaxf(preg[i4 * 4 + 2], preg[i4 * 4 + 3])));
        }
        lmax = fmaxf(lmax, __shfl_xor_sync(0xffffffffu, lmax, 1));
        lmax = fmaxf(lmax, __shfl_xor_sync(0xffffffffu, lmax, 2));
        lmax = fmaxf(lmax, __shfl_xor_sync(0xffffffffu, lmax, 4));
        float mn = fmaxf(mrun, lmax);
        float scl = ex2f(mrun - mn);
        mrun = mn;

        float lsum = 0.f;
#pragma unroll
        for (int i = 0; i < 16; ++i) {
            preg[i] = ex2f(preg[i] - mn);
            lsum += preg[i];
        }
        lsum += __shfl_xor_sync(0xffffffffu, lsum, 1);
        lsum += __shfl_xor_sync(0xffffffffu, lsum, 2);
        lsum += __shfl_xor_sync(0xffffffffu, lsum, 4);
        lrun = fmaf(lrun, scl, lsum);

        {   // store weights t-major (stride 132)
            float4* wd = (float4*)&S[ASW + tq * 132 + csub * 16];
            wd[0] = make_float4(preg[0], preg[1], preg[2], preg[3]);
            wd[1] = make_float4(preg[4], preg[5], preg[6], preg[7]);
            wd[2] = make_float4(preg[8], preg[9], preg[10], preg[11]);
            wd[3] = make_float4(preg[12], preg[13], preg[14], preg[15]);
        }
        if (csub == 0) S[ASSC + tq] = scl;
        __syncthreads();

        // ---- rescale accumulators ----
#pragma unroll
        for (int i = 0; i < 4; ++i) {
            ull sc = dup2(S[ASSC + tg + 8 * i]);
#pragma unroll
            for (int d2 = 0; d2 < 4; ++d2) acc[i][d2] = mul2(acc[i][d2], sc);
        }

        // ---- value GEMM: warp covers contexts wid*16 .. wid*16+16 ----
#pragma unroll
        for (int k4 = 0; k4 < 4; ++k4) {
            int c0 = wid * 16 + k4 * 4;
            float4 wv0 = *(const float4*)&S[ASW + (tg     ) * 132 + c0];
            float4 wv1 = *(const float4*)&S[ASW + (tg +  8) * 132 + c0];
            float4 wv2 = *(const float4*)&S[ASW + (tg + 16) * 132 + c0];
            float4 wv3 = *(const float4*)&S[ASW + (tg + 24) * 132 + c0];
#define DO_CI(CI, COMP)                                                        \
            {                                                                  \
                const float* yp = &S[ASYC + (c0 + CI) * 32 + dg * 8];          \
                ulonglong2 ya = *(const ulonglong2*)yp;                        \
                ulonglong2 yb = *(const ulonglong2*)(yp + 4);                  \
                ull w;                                                         \
                w = dup2(wv0.COMP);                                            \
                fma2(acc[0][0], ya.x, w); fma2(acc[0][1], ya.y, w);            \
                fma2(acc[0][2], yb.x, w); fma2(acc[0][3], yb.y, w);            \
                w = dup2(wv1.COMP);                                            \
                fma2(acc[1][0], ya.x, w); fma2(acc[1][1], ya.y, w);            \
                fma2(acc[1][2], yb.x, w); fma2(acc[1][3], yb.y, w);            \
                w = dup2(wv2.COMP);                                            \
                fma2(acc[2][0], ya.x, w); fma2(acc[2][1], ya.y, w);            \
                fma2(acc[2][2], yb.x, w); fma2(acc[2][3], yb.y, w);            \
                w = dup2(wv3.COMP);                                            \
                fma2(acc[3][0], ya.x, w); fma2(acc[3][1], ya.y, w);            \
                fma2(acc[3][2], yb.x, w); fma2(acc[3][3], yb.y, w);            \
            }
            DO_CI(0, x) DO_CI(1, y) DO_CI(2, z) DO_CI(3, w)
#undef DO_CI
        }
    }
    __syncthreads();   // AKV/ASYC dead; reuse as reduce buffers

    int pidx = (z * B_SZ + b) * NT + t0;
    if (csub == 0) {
        g_pm[pidx + tq] = mrun;
        g_pl[pidx + tq] = lrun;
    }

    // 8-way c-split reduction: warps 0-3 store, 4-7 add
    if (wid < 4) {
#pragma unroll
        for (int i = 0; i < 4; ++i) {
            int t = tg + 8 * i;
            ulonglong2* dst = (ulonglong2*)&S[ARED + wid * 1024 + t * 32 + dg * 8];
            ulonglong2 v0, v1;
            v0.x = acc[i][0]; v0.y = acc[i][1];
            v1.x = acc[i][2]; v1.y = acc[i][3];
            dst[0] = v0; dst[1] = v1;
        }
    }
    __syncthreads();
    if (wid >= 4) {
#pragma unroll
        for (int i = 0; i < 4; ++i) {
            int t = tg + 8 * i;
            ulonglong2* p = (ulonglong2*)&S[ARED + (wid - 4) * 1024 + t * 32 + dg * 8];
            ulonglong2 v0 = p[0], v1 = p[1];
            v0.x = add2(v0.x, acc[i][0]); v0.y = add2(v0.y, acc[i][1]);
            v1.x = add2(v1.x, acc[i][2]); v1.y = add2(v1.y, acc[i][3]);
            p[0] = v0; p[1] = v1;
        }
    }
    __syncthreads();

    {   // sum 4 buffers, write unnormalized partial
        int t = tid >> 3, d8 = tid & 7;
        ull r0 = 0ull, r1 = 0ull;
#pragma unroll
        for (int sI = 0; sI < 4; ++sI) {
            ulonglong2 v = *(const ulonglong2*)&S[ARED + sI * 1024 + t * 32 + d8 * 4];
            r0 = add2(r0, v.x);
            r1 = add2(r1, v.y);
        }
        ulonglong2 o; o.x = r0; o.y = r1;
        *(ulonglong2*)&g_pacc[(pidx + t) * 32 + d8 * 4] = o;
    }
}

// ======================= Kernel 3: combine context halves ==================
// 256 blocks x 256 threads: thread = (target, dim-quad-pair)

__global__ void __launch_bounds__(256)
combine_kernel(float* __restrict__ out) {
    int tid = threadIdx.x;
    int bt = blockIdx.x * 32 + (tid >> 3);   // global (b*NT + t)
    int d8 = tid & 7;

    float m0 = g_pm[bt], m1 = g_pm[B_SZ * NT + bt];
    float l0 = g_pl[bt], l1 = g_pl[B_SZ * NT + bt];
    float M = fmaxf(m0, m1);
    float s0 = ex2f(m0 - M), s1 = ex2f(m1 - M);
    float inv = 1.0f / fmaf(l0, s0, l1 * s1);

    float4 a0 = *(const float4*)&g_pacc[bt * 32 + d8 * 4];
    float4 a1 = *(const float4*)&g_pacc[(B_SZ * NT + bt) * 32 + d8 * 4];
    float4 o;
    o.x = fmaf(a0.x, s0, a1.x * s1) * inv;
    o.y = fmaf(a0.y, s0, a1.y * s1) * inv;
    o.z = fmaf(a0.z, s0, a1.z * s1) * inv;
    o.w = fmaf(a0.w, s0, a1.w * s1) * inv;
    *(float4*)&out[bt * 32 + d8 * 4] = o;
}

// ============================== launch =====================================
extern "C" void kernel_launch(void* const* d_in, const int* in_sizes, int n_in,
                              void* d_out, int out_size) {
    (void)in_sizes; (void)n_in; (void)out_size;
    const float* xc = (const float*)d_in[0];
    const float* yc = (const float*)d_in[1];
    const float* xt = (const float*)d_in[2];
    const float* W0 = (const float*)d_in[3];
    const float* b0 = (const float*)d_in[4];
    const float* W1 = (const float*)d_in[5];
    const float* b1 = (const float*)d_in[6];
    const float* W2 = (const float*)d_in[7];
    const float* b2 = (const float*)d_in[8];
    const float* W3 = (const float*)d_in[9];
    const float* b3 = (const float*)d_in[10];
    float* out = (float*)d_out;

    size_t smem1 = SMEM1_FLOATS * sizeof(float);
    cudaFuncSetAttribute(mlp_kernel, cudaFuncAttributeMaxDynamicSharedMemorySize,
                         (int)smem1);

    mlp_kernel<<<256, TPB1, smem1>>>(xt, W0, b0, W1, b1, W2, b2, W3, b3);
    attn_kernel<<<dim3(NT / 32, B_SZ, 2), 256>>>(xc, yc);
    combine_kernel<<<256, 256>>>(out);
}

// round 12
// speedup vs baseline: 1.4051x; 1.3070x over previous
#include <cuda_runtime.h>
#include <math.h>

// ---------------------------------------------------------------------------
// B=8, Nc=1024, Nt=1024, Dx=3, Dy=32, H=128
// inputs: xc, yc, xt, W0, b0, W1, b1, W2, b2, W3, b3 (all f32)
// out: (B, Nt, 32) f32
// ---------------------------------------------------------------------------

#define B_SZ 8
#define NC 1024
#define NT 1024

typedef unsigned long long ull;

// q[0..2]=2*sig*xt*L2E, q[3..5]=-sig*L2E, q[6]=-(sum sig*xt^2)*L2E
__device__ float g_q[B_SZ * NT * 8];

// ---------------- packed f32x2 helpers (Blackwell FFMA2) -------------------
__device__ __forceinline__ ull dup2(float x) {
    ull r; asm("mov.b64 %0, {%1, %1};" : "=l"(r) : "f"(x)); return r;
}
__device__ __forceinline__ void fma2(ull& d, ull a, ull b) {
    asm("fma.rn.f32x2 %0, %1, %2, %0;" : "+l"(d) : "l"(a), "l"(b));
}
__device__ __forceinline__ ull mul2(ull a, ull b) {
    ull r; asm("mul.rn.f32x2 %0, %1, %2;" : "=l"(r) : "l"(a), "l"(b)); return r;
}
__device__ __forceinline__ ull add2(ull a, ull b) {
    ull r; asm("add.rn.f32x2 %0, %1, %2;" : "=l"(r) : "l"(a), "l"(b)); return r;
}
__device__ __forceinline__ void unpack2(ull v, float& lo, float& hi) {
    asm("mov.b64 {%0, %1}, %2;" : "=f"(lo), "=f"(hi) : "l"(v));
}
__device__ __forceinline__ float ex2f(float x) {
    float y; asm("ex2.approx.ftz.f32 %0, %1;" : "=f"(y) : "f"(x)); return y;
}

// ======================= Kernel 1: MLP -> sigma -> q =======================
// 512 blocks x 256 threads, 16 points/block, 4 blocks/SM (one full wave).
// Thread owns unit j (0..127) for 8 points of group g (0..1).
// W streamed from L2 in 16-row chunks via 2 x 8KB ping-pong smem buffers.
// Activation row stride HS = 20 floats (80B, 16B-aligned).
//
// Shared layout (floats), total 10496 = 41984 B:
//   oWb0    0  (2048)   weight chunk buf 0 (16 rows x 128)
//   oWb1 2048  (2048)   weight chunk buf 1
//   ohA  4096  (2560)   activations A (128 units x HS)
//   ohB  6656  (2560)   activations B
//   oW0  9216  ( 384)
//   oW3  9600  ( 384)
//   ob0  9984  ( 128)
//   ob1 10112  ( 128)
//   ob2 10240  ( 128)
//   ob3 10368  (  16)
//   oxt 10384  (  48)
//   oso 10432  (  64)

#define TPB1 256
#define HS   20
#define oWb0 0
#define oWb1 2048
#define ohA  4096
#define ohB  6656
#define oW0  9216
#define oW3  9600
#define ob0  9984
#define ob1  10112
#define ob2  10240
#define ob3  10368
#define oxt  10384
#define oso  10432
#define SMEM1_FLOATS 10496

__device__ __forceinline__ void cp4(float* dst, const float* src, int n4, int tid) {
    const float4* s4 = (const float4*)src;
    float4* d4 = (float4*)dst;
    for (int i = tid; i < n4; i += TPB1) d4[i] = s4[i];
}

// One 128->128 layer, weights streamed in 8 chunks of 16 rows (2048 floats).
// Wg = this layer's weights; Wnext (may be null) has its chunk 0 prefetched
// during the last chunk.
__device__ __forceinline__ void hidden_chunked(
    float* S, int oin, int oout, const float* __restrict__ Wg,
    const float* __restrict__ Wnext, int ob, int g, int j, int tid) {
    ull A0, A1, A2, A3;
    A0 = A1 = A2 = A3 = dup2(S[ob + j]);
#pragma unroll
    for (int q = 0; q < 8; ++q) {
        float4 pre0, pre1;
        const float4* src = 0;
        if (q < 7)      src = (const float4*)(Wg + (q + 1) * 2048);
        else if (Wnext) src = (const float4*)Wnext;
        if (src) { pre0 = src[tid]; pre1 = src[tid + 256]; }
        const float* Wb = &S[(q & 1) ? oWb1 : oWb0];
        const float* ain = &S[oin + q * 16 * HS + g * 8];
#pragma unroll
        for (int k2 = 0; k2 < 16; ++k2) {
            ulonglong2 p01 = *(const ulonglong2*)(ain + k2 * HS);
            ulonglong2 p23 = *(const ulonglong2*)(ain + k2 * HS + 4);
            ull w = dup2(Wb[k2 * 128 + j]);
            fma2(A0, p01.x, w); fma2(A1, p01.y, w);
            fma2(A2, p23.x, w); fma2(A3, p23.y, w);
        }
        if (src) {
            float4* dst = (float4*)&S[(q & 1) ? oWb0 : oWb1];
            dst[tid] = pre0; dst[tid + 256] = pre1;
        }
        __syncthreads();
    }
    float v[8];
    unpack2(A0, v[0], v[1]); unpack2(A1, v[2], v[3]);
    unpack2(A2, v[4], v[5]); unpack2(A3, v[6], v[7]);
    float4* r = (float4*)&S[oout + j * HS + g * 8];
    r[0] = make_float4(fmaxf(v[0], 0.f), fmaxf(v[1], 0.f), fmaxf(v[2], 0.f), fmaxf(v[3], 0.f));
    r[1] = make_float4(fmaxf(v[4], 0.f), fmaxf(v[5], 0.f), fmaxf(v[6], 0.f), fmaxf(v[7], 0.f));
    __syncthreads();
}

__global__ void __launch_bounds__(TPB1, 4)
mlp_kernel(const float* __restrict__ xt,
           const float* __restrict__ W0, const float* __restrict__ b0,
           const float* __restrict__ W1, const float* __restrict__ b1,
           const float* __restrict__ W2, const float* __restrict__ b2,
           const float* __restrict__ W3, const float* __restrict__ b3) {
    extern __shared__ float S[];
    int tid = threadIdx.x;
    int wid = tid >> 5, lane = tid & 31;
    int g = tid >> 7;   // 2 groups x 8 points
    int j = tid & 127;  // unit

    {   // W1 chunk 0 (16 rows = 2048 floats = 512 float4) -> buf0
        const float4* s4 = (const float4*)W1;
        float4* d4 = (float4*)&S[oWb0];
        d4[tid] = s4[tid];
        d4[tid + 256] = s4[tid + 256];
    }
    cp4(&S[oW0], W0, 96, tid);     // 384 floats
    cp4(&S[oW3], W3, 96, tid);     // 384 floats
    cp4(&S[ob0], b0, 32, tid);     // 128 floats
    cp4(&S[ob1], b1, 32, tid);
    cp4(&S[ob2], b2, 32, tid);
    if (tid < 3) S[ob3 + tid] = b3[tid];

    int pbase = blockIdx.x * 16;
    if (tid < 48) S[oxt + tid] = xt[pbase * 3 + tid];
    __syncthreads();

    {   // layer 0: 3 -> 128 (thread = unit j, group g, 8 points)
        float bb = S[ob0 + j];
        float w0 = S[oW0 + j], w1 = S[oW0 + 128 + j], w2 = S[oW0 + 256 + j];
        float a[8];
#pragma unroll
        for (int p = 0; p < 8; ++p) {
            int lp = g * 8 + p;
            float x0 = S[oxt + lp * 3 + 0];
            float x1 = S[oxt + lp * 3 + 1];
            float x2 = S[oxt + lp * 3 + 2];
            a[p] = fmaxf(fmaf(x2, w2, fmaf(x1, w1, fmaf(x0, w0, bb))), 0.f);
        }
        float4* r = (float4*)&S[ohA + j * HS + g * 8];
        r[0] = make_float4(a[0], a[1], a[2], a[3]);
        r[1] = make_float4(a[4], a[5], a[6], a[7]);
    }
    __syncthreads();

    hidden_chunked(S, ohA, ohB, W1, W2, ob1, g, j, tid);   // layer 1
    hidden_chunked(S, ohB, ohA, W2, 0,  ob2, g, j, tid);   // layer 2

    // output layer 128 -> 3: warps 0..2 (d = wid), lane = point (16 used)
    if (wid < 3 && lane < 16) {
        int d = wid;
        float a0 = 0.f, a1 = 0.f, a2 = 0.f, a3 = 0.f;
#pragma unroll 4
        for (int k = 0; k < 128; k += 4) {
            a0 = fmaf(S[ohA + (k + 0) * HS + lane], S[oW3 + (k + 0) * 3 + d], a0);
            a1 = fmaf(S[ohA + (k + 1) * HS + lane], S[oW3 + (k + 1) * 3 + d], a1);
            a2 = fmaf(S[ohA + (k + 2) * HS + lane], S[oW3 + (k + 2) * 3 + d], a2);
            a3 = fmaf(S[ohA + (k + 3) * HS + lane], S[oW3 + (k + 3) * 3 + d], a3);
        }
        S[oso + lane * 4 + d] = S[ob3 + d] + ((a0 + a1) + (a2 + a3));
    }
    __syncthreads();

    if (tid < 16) {   // epilogue: sigma = exp(o), build q (log2 domain)
        float o0 = S[oso + tid * 4 + 0];
        float o1 = S[oso + tid * 4 + 1];
        float o2 = S[oso + tid * 4 + 2];
        float s0 = expf(o0), s1 = expf(o1), s2 = expf(o2);
        float x0 = S[oxt + tid * 3 + 0];
        float x1 = S[oxt + tid * 3 + 1];
        float x2 = S[oxt + tid * 3 + 2];
        const float L2E = 1.44269504088896340736f;
        float c6 = -(s0 * x0 * x0 + s1 * x1 * x1 + s2 * x2 * x2) * L2E;
        float4* qd = (float4*)&g_q[(pbase + tid) * 8];
        qd[0] = make_float4(2.f * s0 * x0 * L2E, 2.f * s1 * x1 * L2E,
                            2.f * s2 * x2 * L2E, -s0 * L2E);
        qd[1] = make_float4(-s1 * L2E, -s2 * L2E, c6, 0.f);
    }
}

// ======================= Kernel 2: streaming softmax-attention =============
// (verbatim the R4-benched 27us version)

#define AKV 0        /* 6 x 128 SoA key features */
#define ASYC 1024    /* 128 x 32 values */
#define ASW 5120     /* 128 x 36 weights */
#define ASQ 9728     /* 32 x 8 queries */
#define ASMX 9984
#define ASL 10016
#define ASSC 10048
#define ARMX 10080   /* 256 */
#define ARSM 10336   /* 256 */
#define ARED 1024    /* 8 x 32 x 32 reduce buffer (reuses ASYC/ASW) */
#define ATOT 10592

__global__ void __launch_bounds__(256, 2)
attn_kernel(const float* __restrict__ xc, const float* __restrict__ yc,
            float* __restrict__ out) {
    __shared__ __align__(16) float S[ATOT];

    int tid = threadIdx.x;
    int b = blockIdx.y;
    int t0 = blockIdx.x * 32;

    S[ASQ + tid] = g_q[(b * NT + t0) * 8 + tid];
    if (tid < 32) { S[ASMX + tid] = -1e30f; S[ASL + tid] = 0.f; }
    __syncthreads();

    int tP = tid & 31, cg = tid >> 5;                    // logit mapping
    float q0 = S[ASQ + tP * 8 + 0], q1 = S[ASQ + tP * 8 + 1];
    float q2 = S[ASQ + tP * 8 + 2], q3 = S[ASQ + tP * 8 + 3];
    float q4 = S[ASQ + tP * 8 + 4], q5 = S[ASQ + tP * 8 + 5];
    float q6 = S[ASQ + tP * 8 + 6];

    int s16 = tid >> 4, u = tid & 15, tg = u >> 2, dg = u & 3;  // GEMM mapping

    ull acc[8][4];
#pragma unroll
    for (int i = 0; i < 8; ++i)
#pragma unroll
        for (int jj = 0; jj < 4; ++jj) acc[i][jj] = 0ull;

    for (int ch = 0; ch < 8; ++ch) {
        int cbase = ch * 128;
        __syncthreads();   // prior GEMM reads done before overwrite

        if (tid < 128) {
            const float* xp = &xc[(b * NC + cbase + tid) * 3];
            float x0 = xp[0], x1 = xp[1], x2 = xp[2];
            S[AKV + tid] = x0;
            S[AKV + 128 + tid] = x1;
            S[AKV + 256 + tid] = x2;
            S[AKV + 384 + tid] = x0 * x0;
            S[AKV + 512 + tid] = x1 * x1;
            S[AKV + 640 + tid] = x2 * x2;
        }
        {
            const float4* ys = (const float4*)&yc[(b * NC + cbase) * 32];
            float4* yd = (float4*)&S[ASYC];
#pragma unroll
            for (int r = 0; r < 4; ++r) yd[tid + 256 * r] = ys[tid + 256 * r];
        }
        __syncthreads();

        // ---- logits (log2 units), paired over contexts ----
        float preg[16];
        float lmax = -1e30f;
        ull q0d = dup2(q0), q1d = dup2(q1), q2d = dup2(q2);
        ull q3d = dup2(q3), q4d = dup2(q4), q5d = dup2(q5);
        ull q6d = dup2(q6);
#pragma unroll
        for (int i4 = 0; i4 < 4; ++i4) {
            int c0 = cg * 16 + i4 * 4;
            ulonglong2 f0 = *(const ulonglong2*)&S[AKV + c0];
            ulonglong2 f1 = *(const ulonglong2*)&S[AKV + 128 + c0];
            ulonglong2 f2 = *(const ulonglong2*)&S[AKV + 256 + c0];
            ulonglong2 f3 = *(const ulonglong2*)&S[AKV + 384 + c0];
            ulonglong2 f4 = *(const ulonglong2*)&S[AKV + 512 + c0];
            ulonglong2 f5 = *(const ulonglong2*)&S[AKV + 640 + c0];
            ull P01 = q6d, P23 = q6d;
            fma2(P01, f0.x, q0d); fma2(P23, f0.y, q0d);
            fma2(P01, f1.x, q1d); fma2(P23, f1.y, q1d);
            fma2(P01, f2.x, q2d); fma2(P23, f2.y, q2d);
            fma2(P01, f3.x, q3d); fma2(P23, f3.y, q3d);
            fma2(P01, f4.x, q4d); fma2(P23, f4.y, q4d);
            fma2(P01, f5.x, q5d); fma2(P23, f5.y, q5d);
            unpack2(P01, preg[i4 * 4 + 0], preg[i4 * 4 + 1]);
            unpack2(P23, preg[i4 * 4 + 2], preg[i4 * 4 + 3]);
            lmax = fmaxf(lmax, fmaxf(fmaxf(preg[i4 * 4], preg[i4 * 4 + 1]),
                                     fmaxf(preg[i4 * 4 + 2], preg[i4 * 4 + 3])));
        }
        S[ARMX + cg * 32 + tP] = lmax;
        __syncthreads();

        if (tid < 32) {
            float m = S[ARMX + tid];
#pragma unroll
            for (int g2 = 1; g2 < 8; ++g2) m = fmaxf(m, S[ARMX + g2 * 32 + tid]);
            float mo = S[ASMX + tid], mn = fmaxf(mo, m);
            S[ASSC + tid] = ex2f(mo - mn);
            S[ASMX + tid] = mn;
        }
        __syncthreads();

        // rescale accumulators
#pragma unroll
        for (int wi = 0; wi < 8; ++wi) {
            ull scd = dup2(S[ASSC + tg * 8 + wi]);
#pragma unroll
            for (int dj = 0; dj < 4; ++dj) acc[wi][dj] = mul2(acc[wi][dj], scd);
        }

        // ---- weights + row sums ----
        {
            float m = S[ASMX + tP];
            float lsum = 0.f;
#pragma unroll
            for (int i = 0; i < 16; ++i) {
                float w = ex2f(preg[i] - m);
                lsum += w;
                S[ASW + (cg * 16 + i) * 36 + tP] = w;
            }
            S[ARSM + cg * 32 + tP] = lsum;
        }
        __syncthreads();

        if (tid < 32) {
            float sum = S[ARSM + tid];
#pragma unroll
            for (int g2 = 1; g2 < 8; ++g2) sum += S[ARSM + g2 * 32 + tid];
            S[ASL + tid] = fmaf(S[ASL + tid], S[ASSC + tid], sum);
        }

        // ---- value GEMM: acc[t][dpair] += w[c][t]*y[c][dpair] ----
#pragma unroll
        for (int k = 0; k < 8; ++k) {
            int c = s16 * 8 + k;
            float4 wa = *(const float4*)&S[ASW + c * 36 + tg * 8];
            float4 wb = *(const float4*)&S[ASW + c * 36 + tg * 8 + 4];
            ulonglong2 ya = *(const ulonglong2*)&S[ASYC + c * 32 + dg * 8];
            ulonglong2 yb = *(const ulonglong2*)&S[ASYC + c * 32 + dg * 8 + 4];
            ull w;
            w = dup2(wa.x);
            fma2(acc[0][0], ya.x, w); fma2(acc[0][1], ya.y, w);
            fma2(acc[0][2], yb.x, w); fma2(acc[0][3], yb.y, w);
            w = dup2(wa.y);
            fma2(acc[1][0], ya.x, w); fma2(acc[1][1], ya.y, w);
            fma2(acc[1][2], yb.x, w); fma2(acc[1][3], yb.y, w);
            w = dup2(wa.z);
            fma2(acc[2][0], ya.x, w); fma2(acc[2][1], ya.y, w);
            fma2(acc[2][2], yb.x, w); fma2(acc[2][3], yb.y, w);
            w = dup2(wa.w);
            fma2(acc[3][0], ya.x, w); fma2(acc[3][1], ya.y, w);
            fma2(acc[3][2], yb.x, w); fma2(acc[3][3], yb.y, w);
            w = dup2(wb.x);
            fma2(acc[4][0], ya.x, w); fma2(acc[4][1], ya.y, w);
            fma2(acc[4][2], yb.x, w); fma2(acc[4][3], yb.y, w);
            w = dup2(wb.y);
            fma2(acc[5][0], ya.x, w); fma2(acc[5][1], ya.y, w);
            fma2(acc[5][2], yb.x, w); fma2(acc[5][3], yb.y, w);
            w = dup2(wb.z);
            fma2(acc[6][0], ya.x, w); fma2(acc[6][1], ya.y, w);
            fma2(acc[6][2], yb.x, w); fma2(acc[6][3], yb.y, w);
            w = dup2(wb.w);
            fma2(acc[7][0], ya.x, w); fma2(acc[7][1], ya.y, w);
            fma2(acc[7][2], yb.x, w); fma2(acc[7][3], yb.y, w);
        }
    }
    __syncthreads();

    // ---- 16-way split reduction (two phases into 8 buffers) ----
    if (s16 < 8) {
#pragma unroll
        for (int wi = 0; wi < 8; ++wi) {
            int t = tg * 8 + wi;
            ulonglong2* dst = (ulonglong2*)&S[ARED + s16 * 1024 + t * 32 + dg * 8];
            ulonglong2 v0; v0.x = acc[wi][0]; v0.y = acc[wi][1];
            ulonglong2 v1; v1.x = acc[wi][2]; v1.y = acc[wi][3];
            dst[0] = v0; dst[1] = v1;
        }
    }
    __syncthreads();
    if (s16 >= 8) {
        int sI = s16 - 8;
#pragma unroll
        for (int wi = 0; wi < 8; ++wi) {
            int t = tg * 8 + wi;
            ulonglong2* p = (ulonglong2*)&S[ARED + sI * 1024 + t * 32 + dg * 8];
            ulonglong2 v0 = p[0], v1 = p[1];
            v0.x = add2(v0.x, acc[wi][0]); v0.y = add2(v0.y, acc[wi][1]);
            v1.x = add2(v1.x, acc[wi][2]); v1.y = add2(v1.y, acc[wi][3]);
            p[0] = v0; p[1] = v1;
        }
    }
    __syncthreads();

    {
        int t = tid >> 3, dq = tid & 7;
        ull r0 = 0ull, r1 = 0ull;
#pragma unroll
        for (int sI = 0; sI < 8; ++sI) {
            ulonglong2 v = *(const ulonglong2*)&S[ARED + sI * 1024 + t * 32 + dq * 4];
            r0 = add2(r0, v.x);
            r1 = add2(r1, v.y);
        }
        ull invd = dup2(1.0f / S[ASL + t]);
        r0 = mul2(r0, invd);
        r1 = mul2(r1, invd);
        ulonglong2 o; o.x = r0; o.y = r1;
        *(ulonglong2*)&out[(b * NT + t0 + t) * 32 + dq * 4] = o;
    }
}

// ============================== launch =====================================
extern "C" void kernel_launch(void* const* d_in, const int* in_sizes, int n_in,
                              void* d_out, int out_size) {
    (void)in_sizes; (void)n_in; (void)out_size;
    const float* xc = (const float*)d_in[0];
    const float* yc = (const float*)d_in[1];
    const float* xt = (const float*)d_in[2];
    const float* W0 = (const float*)d_in[3];
    const float* b0 = (const float*)d_in[4];
    const float* W1 = (const float*)d_in[5];
    const float* b1 = (const float*)d_in[6];
    const float* W2 = (const float*)d_in[7];
    const float* b2 = (const float*)d_in[8];
    const float* W3 = (const float*)d_in[9];
    const float* b3 = (const float*)d_in[10];
    float* out = (float*)d_out;

    size_t smem1 = SMEM1_FLOATS * sizeof(float);
    cudaFuncSetAttribute(mlp_kernel, cudaFuncAttributeMaxDynamicSharedMemorySize,
                         (int)smem1);

    mlp_kernel<<<512, TPB1, smem1>>>(xt, W0, b0, W1, b1, W2, b2, W3, b3);
    attn_kernel<<<dim3(NT / 32, B_SZ), 256>>>(xc, yc, out);
}

// round 15
// speedup vs baseline: 1.4309x; 1.0184x over previous
#include <cuda_runtime.h>
#include <math.h>

// ---------------------------------------------------------------------------
// B=8, Nc=1024, Nt=1024, Dx=3, Dy=32, H=128
// inputs: xc, yc, xt, W0, b0, W1, b1, W2, b2, W3, b3 (all f32)
// out: (B, Nt, 32) f32
// ---------------------------------------------------------------------------

#define B_SZ 8
#define NC 1024
#define NT 1024

typedef unsigned long long ull;

// q[0..2]=2*sig*xt*L2E, q[3..5]=-sig*L2E, q[6]=-(sum sig*xt^2)*L2E
__device__ float g_q[B_SZ * NT * 8];

// ---------------- packed f32x2 helpers (Blackwell FFMA2) -------------------
__device__ __forceinline__ ull dup2(float x) {
    ull r; asm("mov.b64 %0, {%1, %1};" : "=l"(r) : "f"(x)); return r;
}
__device__ __forceinline__ void fma2(ull& d, ull a, ull b) {
    asm("fma.rn.f32x2 %0, %1, %2, %0;" : "+l"(d) : "l"(a), "l"(b));
}
__device__ __forceinline__ ull mul2(ull a, ull b) {
    ull r; asm("mul.rn.f32x2 %0, %1, %2;" : "=l"(r) : "l"(a), "l"(b)); return r;
}
__device__ __forceinline__ ull add2(ull a, ull b) {
    ull r; asm("add.rn.f32x2 %0, %1, %2;" : "=l"(r) : "l"(a), "l"(b)); return r;
}
__device__ __forceinline__ void unpack2(ull v, float& lo, float& hi) {
    asm("mov.b64 {%0, %1}, %2;" : "=f"(lo), "=f"(hi) : "l"(v));
}
__device__ __forceinline__ float ex2f(float x) {
    float y; asm("ex2.approx.ftz.f32 %0, %1;" : "=f"(y) : "f"(x)); return y;
}

// ======================= Kernel 1: MLP -> sigma -> q =======================
// 512 blocks x 256 threads, 16 points/block, 3 blocks/SM (85-reg budget,
// no spills). Thread owns unit j (0..127) for 8 points of group g (0..1).
// W streamed from L2 in 16-row chunks via 2 x 8KB ping-pong smem buffers.
// Activation row stride HS = 20 floats (80B, 16B-aligned).

#define TPB1 256
#define HS   20
#define oWb0 0
#define oWb1 2048
#define ohA  4096
#define ohB  6656
#define oW0  9216
#define oW3  9600
#define ob0  9984
#define ob1  10112
#define ob2  10240
#define ob3  10368
#define oxt  10384
#define oso  10432
#define SMEM1_FLOATS 10496

__device__ __forceinline__ void cp4(float* dst, const float* src, int n4, int tid) {
    const float4* s4 = (const float4*)src;
    float4* d4 = (float4*)dst;
    for (int i = tid; i < n4; i += TPB1) d4[i] = s4[i];
}

// One 128->128 layer, weights streamed in 8 chunks of 16 rows (2048 floats).
// Wg = this layer's weights; Wnext (may be null) has its chunk 0 prefetched
// during the last chunk.
__device__ __forceinline__ void hidden_chunked(
    float* S, int oin, int oout, const float* __restrict__ Wg,
    const float* __restrict__ Wnext, int ob, int g, int j, int tid) {
    ull A0, A1, A2, A3;
    A0 = A1 = A2 = A3 = dup2(S[ob + j]);
#pragma unroll
    for (int q = 0; q < 8; ++q) {
        float4 pre0, pre1;
        const float4* src = 0;
        if (q < 7)      src = (const float4*)(Wg + (q + 1) * 2048);
        else if (Wnext) src = (const float4*)Wnext;
        if (src) { pre0 = src[tid]; pre1 = src[tid + 256]; }
        const float* Wb = &S[(q & 1) ? oWb1 : oWb0];
        const float* ain = &S[oin + q * 16 * HS + g * 8];
#pragma unroll
        for (int k2 = 0; k2 < 16; ++k2) {
            ulonglong2 p01 = *(const ulonglong2*)(ain + k2 * HS);
            ulonglong2 p23 = *(const ulonglong2*)(ain + k2 * HS + 4);
            ull w = dup2(Wb[k2 * 128 + j]);
            fma2(A0, p01.x, w); fma2(A1, p01.y, w);
            fma2(A2, p23.x, w); fma2(A3, p23.y, w);
        }
        if (src) {
            float4* dst = (float4*)&S[(q & 1) ? oWb0 : oWb1];
            dst[tid] = pre0; dst[tid + 256] = pre1;
        }
        __syncthreads();
    }
    float v[8];
    unpack2(A0, v[0], v[1]); unpack2(A1, v[2], v[3]);
    unpack2(A2, v[4], v[5]); unpack2(A3, v[6], v[7]);
    float4* r = (float4*)&S[oout + j * HS + g * 8];
    r[0] = make_float4(fmaxf(v[0], 0.f), fmaxf(v[1], 0.f), fmaxf(v[2], 0.f), fmaxf(v[3], 0.f));
    r[1] = make_float4(fmaxf(v[4], 0.f), fmaxf(v[5], 0.f), fmaxf(v[6], 0.f), fmaxf(v[7], 0.f));
    __syncthreads();
}

__global__ void __launch_bounds__(TPB1, 3)
mlp_kernel(const float* __restrict__ xt,
           const float* __restrict__ W0, const float* __restrict__ b0,
           const float* __restrict__ W1, const float* __restrict__ b1,
           const float* __restrict__ W2, const float* __restrict__ b2,
           const float* __restrict__ W3, const float* __restrict__ b3) {
    extern __shared__ float S[];
    int tid = threadIdx.x;
    int wid = tid >> 5, lane = tid & 31;
    int g = tid >> 7;   // 2 groups x 8 points
    int j = tid & 127;  // unit

    {   // W1 chunk 0 (16 rows = 2048 floats = 512 float4) -> buf0
        const float4* s4 = (const float4*)W1;
        float4* d4 = (float4*)&S[oWb0];
        d4[tid] = s4[tid];
        d4[tid + 256] = s4[tid + 256];
    }
    cp4(&S[oW0], W0, 96, tid);     // 384 floats
    cp4(&S[oW3], W3, 96, tid);     // 384 floats
    cp4(&S[ob0], b0, 32, tid);     // 128 floats
    cp4(&S[ob1], b1, 32, tid);
    cp4(&S[ob2], b2, 32, tid);
    if (tid < 3) S[ob3 + tid] = b3[tid];

    int pbase = blockIdx.x * 16;
    if (tid < 48) S[oxt + tid] = xt[pbase * 3 + tid];
    __syncthreads();

    {   // layer 0: 3 -> 128 (thread = unit j, group g, 8 points)
        float bb = S[ob0 + j];
        float w0 = S[oW0 + j], w1 = S[oW0 + 128 + j], w2 = S[oW0 + 256 + j];
        float a[8];
#pragma unroll
        for (int p = 0; p < 8; ++p) {
            int lp = g * 8 + p;
            float x0 = S[oxt + lp * 3 + 0];
            float x1 = S[oxt + lp * 3 + 1];
            float x2 = S[oxt + lp * 3 + 2];
            a[p] = fmaxf(fmaf(x2, w2, fmaf(x1, w1, fmaf(x0, w0, bb))), 0.f);
        }
        float4* r = (float4*)&S[ohA + j * HS + g * 8];
        r[0] = make_float4(a[0], a[1], a[2], a[3]);
        r[1] = make_float4(a[4], a[5], a[6], a[7]);
    }
    __syncthreads();

    hidden_chunked(S, ohA, ohB, W1, W2, ob1, g, j, tid);   // layer 1
    hidden_chunked(S, ohB, ohA, W2, 0,  ob2, g, j, tid);   // layer 2

    // output layer 128 -> 3: warps 0..2 (d = wid), lane = point (16 used)
    if (wid < 3 && lane < 16) {
        int d = wid;
        float a0 = 0.f, a1 = 0.f, a2 = 0.f, a3 = 0.f;
#pragma unroll 4
        for (int k = 0; k < 128; k += 4) {
            a0 = fmaf(S[ohA + (k + 0) * HS + lane], S[oW3 + (k + 0) * 3 + d], a0);
            a1 = fmaf(S[ohA + (k + 1) * HS + lane], S[oW3 + (k + 1) * 3 + d], a1);
            a2 = fmaf(S[ohA + (k + 2) * HS + lane], S[oW3 + (k + 2) * 3 + d], a2);
            a3 = fmaf(S[ohA + (k + 3) * HS + lane], S[oW3 + (k + 3) * 3 + d], a3);
        }
        S[oso + lane * 4 + d] = S[ob3 + d] + ((a0 + a1) + (a2 + a3));
    }
    __syncthreads();

    if (tid < 16) {   // epilogue: sigma = exp(o), build q (log2 domain)
        float o0 = S[oso + tid * 4 + 0];
        float o1 = S[oso + tid * 4 + 1];
        float o2 = S[oso + tid * 4 + 2];
        float s0 = expf(o0), s1 = expf(o1), s2 = expf(o2);
        float x0 = S[oxt + tid * 3 + 0];
        float x1 = S[oxt + tid * 3 + 1];
        float x2 = S[oxt + tid * 3 + 2];
        const float L2E = 1.44269504088896340736f;
        float c6 = -(s0 * x0 * x0 + s1 * x1 * x1 + s2 * x2 * x2) * L2E;
        float4* qd = (float4*)&g_q[(pbase + tid) * 8];
        qd[0] = make_float4(2.f * s0 * x0 * L2E, 2.f * s1 * x1 * L2E,
                            2.f * s2 * x2 * L2E, -s0 * L2E);
        qd[1] = make_float4(-s1 * L2E, -s2 * L2E, c6, 0.f);
    }
}

// ======================= Kernel 2: streaming softmax-attention =============
// (verbatim the R4/R12-benched 27.8us version — do not touch)

#define AKV 0        /* 6 x 128 SoA key features */
#define ASYC 1024    /* 128 x 32 values */
#define ASW 5120     /* 128 x 36 weights */
#define ASQ 9728     /* 32 x 8 queries */
#define ASMX 9984
#define ASL 10016
#define ASSC 10048
#define ARMX 10080   /* 256 */
#define ARSM 10336   /* 256 */
#define ARED 1024    /* 8 x 32 x 32 reduce buffer (reuses ASYC/ASW) */
#define ATOT 10592

__global__ void __launch_bounds__(256, 2)
attn_kernel(const float* __restrict__ xc, const float* __restrict__ yc,
            float* __restrict__ out) {
    __shared__ __align__(16) float S[ATOT];

    int tid = threadIdx.x;
    int b = blockIdx.y;
    int t0 = blockIdx.x * 32;

    S[ASQ + tid] = g_q[(b * NT + t0) * 8 + tid];
    if (tid < 32) { S[ASMX + tid] = -1e30f; S[ASL + tid] = 0.f; }
    __syncthreads();

    int tP = tid & 31, cg = tid >> 5;                    // logit mapping
    float q0 = S[ASQ + tP * 8 + 0], q1 = S[ASQ + tP * 8 + 1];
    float q2 = S[ASQ + tP * 8 + 2], q3 = S[ASQ + tP * 8 + 3];
    float q4 = S[ASQ + tP * 8 + 4], q5 = S[ASQ + tP * 8 + 5];
    float q6 = S[ASQ + tP * 8 + 6];

    int s16 = tid >> 4, u = tid & 15, tg = u >> 2, dg = u & 3;  // GEMM mapping

    ull acc[8][4];
#pragma unroll
    for (int i = 0; i < 8; ++i)
#pragma unroll
        for (int jj = 0; jj < 4; ++jj) acc[i][jj] = 0ull;

    for (int ch = 0; ch < 8; ++ch) {
        int cbase = ch * 128;
        __syncthreads();   // prior GEMM reads done before overwrite

        if (tid < 128) {
            const float* xp = &xc[(b * NC + cbase + tid) * 3];
            float x0 = xp[0], x1 = xp[1], x2 = xp[2];
            S[AKV + tid] = x0;
            S[AKV + 128 + tid] = x1;
            S[AKV + 256 + tid] = x2;
            S[AKV + 384 + tid] = x0 * x0;
            S[AKV + 512 + tid] = x1 * x1;
            S[AKV + 640 + tid] = x2 * x2;
        }
        {
            const float4* ys = (const float4*)&yc[(b * NC + cbase) * 32];
            float4* yd = (float4*)&S[ASYC];
#pragma unroll
            for (int r = 0; r < 4; ++r) yd[tid + 256 * r] = ys[tid + 256 * r];
        }
        __syncthreads();

        // ---- logits (log2 units), paired over contexts ----
        float preg[16];
        float lmax = -1e30f;
        ull q0d = dup2(q0), q1d = dup2(q1), q2d = dup2(q2);
        ull q3d = dup2(q3), q4d = dup2(q4), q5d = dup2(q5);
        ull q6d = dup2(q6);
#pragma unroll
        for (int i4 = 0; i4 < 4; ++i4) {
            int c0 = cg * 16 + i4 * 4;
            ulonglong2 f0 = *(const ulonglong2*)&S[AKV + c0];
            ulonglong2 f1 = *(const ulonglong2*)&S[AKV + 128 + c0];
            ulonglong2 f2 = *(const ulonglong2*)&S[AKV + 256 + c0];
            ulonglong2 f3 = *(const ulonglong2*)&S[AKV + 384 + c0];
            ulonglong2 f4 = *(const ulonglong2*)&S[AKV + 512 + c0];
            ulonglong2 f5 = *(const ulonglong2*)&S[AKV + 640 + c0];
            ull P01 = q6d, P23 = q6d;
            fma2(P01, f0.x, q0d); fma2(P23, f0.y, q0d);
            fma2(P01, f1.x, q1d); fma2(P23, f1.y, q1d);
            fma2(P01, f2.x, q2d); fma2(P23, f2.y, q2d);
            fma2(P01, f3.x, q3d); fma2(P23, f3.y, q3d);
            fma2(P01, f4.x, q4d); fma2(P23, f4.y, q4d);
            fma2(P01, f5.x, q5d); fma2(P23, f5.y, q5d);
            unpack2(P01, preg[i4 * 4 + 0], preg[i4 * 4 + 1]);
            unpack2(P23, preg[i4 * 4 + 2], preg[i4 * 4 + 3]);
            lmax = fmaxf(lmax, fmaxf(fmaxf(preg[i4 * 4], preg[i4 * 4 + 1]),
                                     fmaxf(preg[i4 * 4 + 2], preg[i4 * 4 + 3])));
        }
        S[ARMX + cg * 32 + tP] = lmax;
        __syncthreads();

        if (tid < 32) {
            float m = S[ARMX + tid];
#pragma unroll
            for (int g2 = 1; g2 < 8; ++g2) m = fmaxf(m, S[ARMX + g2 * 32 + tid]);
            float mo = S[ASMX + tid], mn = fmaxf(mo, m);
            S[ASSC + tid] = ex2f(mo - mn);
            S[ASMX + tid] = mn;
        }
        __syncthreads();

        // rescale accumulators
#pragma unroll
        for (int wi = 0; wi < 8; ++wi) {
            ull scd = dup2(S[ASSC + tg * 8 + wi]);
#pragma unroll
            for (int dj = 0; dj < 4; ++dj) acc[wi][dj] = mul2(acc[wi][dj], scd);
        }

        // ---- weights + row sums ----
        {
            float m = S[ASMX + tP];
            float lsum = 0.f;
#pragma unroll
            for (int i = 0; i < 16; ++i) {
                float w = ex2f(preg[i] - m);
                lsum += w;
                S[ASW + (cg * 16 + i) * 36 + tP] = w;
            }
            S[ARSM + cg * 32 + tP] = lsum;
        }
        __syncthreads();

        if (tid < 32) {
            float sum = S[ARSM + tid];
#pragma unroll
            for (int g2 = 1; g2 < 8; ++g2) sum += S[ARSM + g2 * 32 + tid];
            S[ASL + tid] = fmaf(S[ASL + tid], S[ASSC + tid], sum);
        }

        // ---- value GEMM: acc[t][dpair] += w[c][t]*y[c][dpair] ----
#pragma unroll
        for (int k = 0; k < 8; ++k) {
            int c = s16 * 8 + k;
            float4 wa = *(const float4*)&S[ASW + c * 36 + tg * 8];
            float4 wb = *(const float4*)&S[ASW + c * 36 + tg * 8 + 4];
            ulonglong2 ya = *(const ulonglong2*)&S[ASYC + c * 32 + dg * 8];
            ulonglong2 yb = *(const ulonglong2*)&S[ASYC + c * 32 + dg * 8 + 4];
            ull w;
            w = dup2(wa.x);
            fma2(acc[0][0], ya.x, w); fma2(acc[0][1], ya.y, w);
            fma2(acc[0][2], yb.x, w); fma2(acc[0][3], yb.y, w);
            w = dup2(wa.y);
            fma2(acc[1][0], ya.x, w); fma2(acc[1][1], ya.y, w);
            fma2(acc[1][2], yb.x, w); fma2(acc[1][3], yb.y, w);
            w = dup2(wa.z);
            fma2(acc[2][0], ya.x, w); fma2(acc[2][1], ya.y, w);
            fma2(acc[2][2], yb.x, w); fma2(acc[2][3], yb.y, w);
            w = dup2(wa.w);
            fma2(acc[3][0], ya.x, w); fma2(acc[3][1], ya.y, w);
            fma2(acc[3][2], yb.x, w); fma2(acc[3][3], yb.y, w);
            w = dup2(wb.x);
            fma2(acc[4][0], ya.x, w); fma2(acc[4][1], ya.y, w);
            fma2(acc[4][2], yb.x, w); fma2(acc[4][3], yb.y, w);
            w = dup2(wb.y);
            fma2(acc[5][0], ya.x, w); fma2(acc[5][1], ya.y, w);
            fma2(acc[5][2], yb.x, w); fma2(acc[5][3], yb.y, w);
            w = dup2(wb.z);
            fma2(acc[6][0], ya.x, w); fma2(acc[6][1], ya.y, w);
            fma2(acc[6][2], yb.x, w); fma2(acc[6][3], yb.y, w);
            w = dup2(wb.w);
            fma2(acc[7][0], ya.x, w); fma2(acc[7][1], ya.y, w);
            fma2(acc[7][2], yb.x, w); fma2(acc[7][3], yb.y, w);
        }
    }
    __syncthreads();

    // ---- 16-way split reduction (two phases into 8 buffers) ----
    if (s16 < 8) {
#pragma unroll
        for (int wi = 0; wi < 8; ++wi) {
            int t = tg * 8 + wi;
            ulonglong2* dst = (ulonglong2*)&S[ARED + s16 * 1024 + t * 32 + dg * 8];
            ulonglong2 v0; v0.x = acc[wi][0]; v0.y = acc[wi][1];
            ulonglong2 v1; v1.x = acc[wi][2]; v1.y = acc[wi][3];
            dst[0] = v0; dst[1] = v1;
        }
    }
    __syncthreads();
    if (s16 >= 8) {
        int sI = s16 - 8;
#pragma unroll
        for (int wi = 0; wi < 8; ++wi) {
            int t = tg * 8 + wi;
            ulonglong2* p = (ulonglong2*)&S[ARED + sI * 1024 + t * 32 + dg * 8];
            ulonglong2 v0 = p[0], v1 = p[1];
            v0.x = add2(v0.x, acc[wi][0]); v0.y = add2(v0.y, acc[wi][1]);
            v1.x = add2(v1.x, acc[wi][2]); v1.y = add2(v1.y, acc[wi][3]);
            p[0] = v0; p[1] = v1;
        }
    }
    __syncthreads();

    {
        int t = tid >> 3, dq = tid & 7;
        ull r0 = 0ull, r1 = 0ull;
#pragma unroll
        for (int sI = 0; sI < 8; ++sI) {
            ulonglong2 v = *(const ulonglong2*)&S[ARED + sI * 1024 + t * 32 + dq * 4];
            r0 = add2(r0, v.x);
            r1 = add2(r1, v.y);
        }
        ull invd = dup2(1.0f / S[ASL + t]);
        r0 = mul2(r0, invd);
        r1 = mul2(r1, invd);
        ulonglong2 o; o.x = r0; o.y = r1;
        *(ulonglong2*)&out[(b * NT + t0 + t) * 32 + dq * 4] = o;
    }
}

// ============================== launch =====================================
extern "C" void kernel_launch(void* const* d_in, const int* in_sizes, int n_in,
                              void* d_out, int out_size) {
    (void)in_sizes; (void)n_in; (void)out_size;
    const float* xc = (const float*)d_in[0];
    const float* yc = (const float*)d_in[1];
    const float* xt = (const float*)d_in[2];
    const float* W0 = (const float*)d_in[3];
    const float* b0 = (const float*)d_in[4];
    const float* W1 = (const float*)d_in[5];
    const float* b1 = (const float*)d_in[6];
    const float* W2 = (const float*)d_in[7];
    const float* b2 = (const float*)d_in[8];
    const float* W3 = (const float*)d_in[9];
    const float* b3 = (const float*)d_in[10];
    float* out = (float*)d_out;

    size_t smem1 = SMEM1_FLOATS * sizeof(float);
    cudaFuncSetAttribute(mlp_kernel, cudaFuncAttributeMaxDynamicSharedMemorySize,
                         (int)smem1);

    mlp_kernel<<<512, TPB1, smem1>>>(xt, W0, b0, W1, b1, W2, b2, W3, b3);
    attn_kernel<<<dim3(NT / 32, B_SZ), 256>>>(xc, yc, out);
}

// round 17
// speedup vs baseline: 1.6772x; 1.1722x over previous
#include <cuda_runtime.h>
#include <math.h>

// ---------------------------------------------------------------------------
// B=8, Nc=1024, Nt=1024, Dx=3, Dy=32, H=128
// inputs: xc, yc, xt, W0, b0, W1, b1, W2, b2, W3, b3 (all f32)
// out: (B, Nt, 32) f32
// ---------------------------------------------------------------------------

#define B_SZ 8
#define NC 1024
#define NT 1024

typedef unsigned long long ull;

// q[0..2]=2*sig*xt*L2E, q[3..5]=-sig*L2E, q[6]=-(sum sig*xt^2)*L2E
__device__ float g_q[B_SZ * NT * 8];

// ---------------- packed f32x2 helpers (Blackwell FFMA2) -------------------
__device__ __forceinline__ ull dup2(float x) {
    ull r; asm("mov.b64 %0, {%1, %1};" : "=l"(r) : "f"(x)); return r;
}
__device__ __forceinline__ void fma2(ull& d, ull a, ull b) {
    asm("fma.rn.f32x2 %0, %1, %2, %0;" : "+l"(d) : "l"(a), "l"(b));
}
__device__ __forceinline__ ull mul2(ull a, ull b) {
    ull r; asm("mul.rn.f32x2 %0, %1, %2;" : "=l"(r) : "l"(a), "l"(b)); return r;
}
__device__ __forceinline__ ull add2(ull a, ull b) {
    ull r; asm("add.rn.f32x2 %0, %1, %2;" : "=l"(r) : "l"(a), "l"(b)); return r;
}
__device__ __forceinline__ void unpack2(ull v, float& lo, float& hi) {
    asm("mov.b64 {%0, %1}, %2;" : "=f"(lo), "=f"(hi) : "l"(v));
}
__device__ __forceinline__ float ex2f(float x) {
    float y; asm("ex2.approx.ftz.f32 %0, %1;" : "=f"(y) : "f"(x)); return y;
}

// ======================= Kernel 1: MLP -> sigma -> q =======================
// R6 version (measured ~22us): 256 blocks x 256 threads, 32 points/block,
// 2 blocks/SM. Thread owns units (j, j+64) for 8 points of group g:
// 8 FFMA2 per k-step against 4 crossbar cycles (balanced). Monolithic 64KB
// weight buffer, W1 then reload W2 (L2-hot).

#define TPB1 256
#define oW   0        /* 16384: W1 then W2 */
#define ohA  16384    /* 128 rows x 36 = 4608 */
#define ohB  20992    /* 4608 */
#define oW0  25600    /* 384 */
#define oW3  25984    /* 384 */
#define ob0  26368    /* 128 */
#define ob1  26496
#define ob2  26624
#define ob3  26752    /* 16 */
#define oxt  26768    /* 96 -> 112 */
#define oso  26880    /* 128 */
#define SMEM1_FLOATS 27008

__device__ __forceinline__ void cp4(float* dst, const float* src, int n4, int tid) {
    const float4* s4 = (const float4*)src;
    float4* d4 = (float4*)dst;
    for (int i = tid; i < n4; i += TPB1) d4[i] = s4[i];
}

__device__ __forceinline__ void hidden_layer(float* S, int oin, int oout,
                                             int ob, int g, int j) {
    ull A0, A1, A2, A3, A4, A5, A6, A7;
    A0 = A1 = A2 = A3 = dup2(S[ob + j]);
    A4 = A5 = A6 = A7 = dup2(S[ob + j + 64]);
#pragma unroll 8
    for (int k = 0; k < 128; ++k) {
        const float* ap = &S[oin + k * 36 + g * 8];
        ulonglong2 p01 = *(const ulonglong2*)ap;
        ulonglong2 p23 = *(const ulonglong2*)(ap + 4);
        ull wa = dup2(S[oW + k * 128 + j]);
        ull wb = dup2(S[oW + k * 128 + j + 64]);
        fma2(A0, p01.x, wa); fma2(A1, p01.y, wa);
        fma2(A2, p23.x, wa); fma2(A3, p23.y, wa);
        fma2(A4, p01.x, wb); fma2(A5, p01.y, wb);
        fma2(A6, p23.x, wb); fma2(A7, p23.y, wb);
    }
    float v[16];
    unpack2(A0, v[0], v[1]);   unpack2(A1, v[2], v[3]);
    unpack2(A2, v[4], v[5]);   unpack2(A3, v[6], v[7]);
    unpack2(A4, v[8], v[9]);   unpack2(A5, v[10], v[11]);
    unpack2(A6, v[12], v[13]); unpack2(A7, v[14], v[15]);
    float4* r0 = (float4*)&S[oout + j * 36 + g * 8];
    r0[0] = make_float4(fmaxf(v[0], 0.f), fmaxf(v[1], 0.f), fmaxf(v[2], 0.f), fmaxf(v[3], 0.f));
    r0[1] = make_float4(fmaxf(v[4], 0.f), fmaxf(v[5], 0.f), fmaxf(v[6], 0.f), fmaxf(v[7], 0.f));
    float4* r1 = (float4*)&S[oout + (j + 64) * 36 + g * 8];
    r1[0] = make_float4(fmaxf(v[8], 0.f), fmaxf(v[9], 0.f), fmaxf(v[10], 0.f), fmaxf(v[11], 0.f));
    r1[1] = make_float4(fmaxf(v[12], 0.f), fmaxf(v[13], 0.f), fmaxf(v[14], 0.f), fmaxf(v[15], 0.f));
}

__global__ void __launch_bounds__(TPB1, 2)
mlp_kernel(const float* __restrict__ xt,
           const float* __restrict__ W0, const float* __restrict__ b0,
           const float* __restrict__ W1, const float* __restrict__ b1,
           const float* __restrict__ W2, const float* __restrict__ b2,
           const float* __restrict__ W3, const float* __restrict__ b3) {
    extern __shared__ float S[];
    int tid = threadIdx.x;
    int wid = tid >> 5, lane = tid & 31;
    int g = tid >> 6;   // 4 groups x 8 points
    int j = tid & 63;   // units j, j+64

    cp4(&S[oW], W1, 4096, tid);
    cp4(&S[oW0], W0, 96, tid);
    cp4(&S[oW3], W3, 96, tid);
    cp4(&S[ob0], b0, 32, tid);
    cp4(&S[ob1], b1, 32, tid);
    cp4(&S[ob2], b2, 32, tid);
    if (tid < 3) S[ob3 + tid] = b3[tid];

    int pbase = blockIdx.x * 32;
    if (tid < 96) S[oxt + tid] = xt[pbase * 3 + tid];
    __syncthreads();

    // layer 0: 3 -> 128
    {
        float bb0 = S[ob0 + j], bb1 = S[ob0 + j + 64];
        float w00 = S[oW0 + j],       w01 = S[oW0 + j + 64];
        float w10 = S[oW0 + 128 + j], w11 = S[oW0 + 128 + j + 64];
        float w20 = S[oW0 + 256 + j], w21 = S[oW0 + 256 + j + 64];
        float a0[8], a1[8];
#pragma unroll
        for (int p = 0; p < 8; ++p) {
            int lp = g * 8 + p;
            float x0 = S[oxt + lp * 3 + 0];
            float x1 = S[oxt + lp * 3 + 1];
            float x2 = S[oxt + lp * 3 + 2];
            a0[p] = fmaxf(fmaf(x2, w20, fmaf(x1, w10, fmaf(x0, w00, bb0))), 0.f);
            a1[p] = fmaxf(fmaf(x2, w21, fmaf(x1, w11, fmaf(x0, w01, bb1))), 0.f);
        }
        float4* r0 = (float4*)&S[ohA + j * 36 + g * 8];
        r0[0] = make_float4(a0[0], a0[1], a0[2], a0[3]);
        r0[1] = make_float4(a0[4], a0[5], a0[6], a0[7]);
        float4* r1 = (float4*)&S[ohA + (j + 64) * 36 + g * 8];
        r1[0] = make_float4(a1[0], a1[1], a1[2], a1[3]);
        r1[1] = make_float4(a1[4], a1[5], a1[6], a1[7]);
    }
    __syncthreads();

    hidden_layer(S, ohA, ohB, ob1, g, j);   // layer 1 (W1)
    __syncthreads();
    cp4(&S[oW], W2, 4096, tid);             // reload with W2 (L2-hot)
    __syncthreads();
    hidden_layer(S, ohB, ohA, ob2, g, j);   // layer 2 (W2)
    __syncthreads();

    // output layer 128 -> 3: warps 0..2, d = wid, lane = point
    if (wid < 3) {
        int d = wid;
        float a0 = 0.f, a1 = 0.f, a2 = 0.f, a3 = 0.f;
#pragma unroll 4
        for (int k = 0; k < 128; k += 4) {
            a0 = fmaf(S[ohA + (k + 0) * 36 + lane], S[oW3 + (k + 0) * 3 + d], a0);
            a1 = fmaf(S[ohA + (k + 1) * 36 + lane], S[oW3 + (k + 1) * 3 + d], a1);
            a2 = fmaf(S[ohA + (k + 2) * 36 + lane], S[oW3 + (k + 2) * 3 + d], a2);
            a3 = fmaf(S[ohA + (k + 3) * 36 + lane], S[oW3 + (k + 3) * 3 + d], a3);
        }
        S[oso + lane * 4 + d] = S[ob3 + d] + ((a0 + a1) + (a2 + a3));
    }
    __syncthreads();

    // epilogue: sigma = exp(o), build q (log2 domain)
    if (tid < 32) {
        float o0 = S[oso + tid * 4 + 0];
        float o1 = S[oso + tid * 4 + 1];
        float o2 = S[oso + tid * 4 + 2];
        float s0 = expf(o0), s1 = expf(o1), s2 = expf(o2);
        float x0 = S[oxt + tid * 3 + 0];
        float x1 = S[oxt + tid * 3 + 1];
        float x2 = S[oxt + tid * 3 + 2];
        const float L2E = 1.44269504088896340736f;
        float c6 = -(s0 * x0 * x0 + s1 * x1 * x1 + s2 * x2 * x2) * L2E;
        float4* qd = (float4*)&g_q[(pbase + tid) * 8];
        qd[0] = make_float4(2.f * s0 * x0 * L2E, 2.f * s1 * x1 * L2E,
                            2.f * s2 * x2 * L2E, -s0 * L2E);
        qd[1] = make_float4(-s1 * L2E, -s2 * L2E, c6, 0.f);
    }
}

// ======================= Kernel 2: streaming softmax-attention =============
// (verbatim the R4/R15-benched 26.8us version — do not touch)

#define AKV 0        /* 6 x 128 SoA key features */
#define ASYC 1024    /* 128 x 32 values */
#define ASW 5120     /* 128 x 36 weights */
#define ASQ 9728     /* 32 x 8 queries */
#define ASMX 9984
#define ASL 10016
#define ASSC 10048
#define ARMX 10080   /* 256 */
#define ARSM 10336   /* 256 */
#define ARED 1024    /* 8 x 32 x 32 reduce buffer (reuses ASYC/ASW) */
#define ATOT 10592

__global__ void __launch_bounds__(256, 2)
attn_kernel(const float* __restrict__ xc, const float* __restrict__ yc,
            float* __restrict__ out) {
    __shared__ __align__(16) float S[ATOT];

    int tid = threadIdx.x;
    int b = blockIdx.y;
    int t0 = blockIdx.x * 32;

    S[ASQ + tid] = g_q[(b * NT + t0) * 8 + tid];
    if (tid < 32) { S[ASMX + tid] = -1e30f; S[ASL + tid] = 0.f; }
    __syncthreads();

    int tP = tid & 31, cg = tid >> 5;                    // logit mapping
    float q0 = S[ASQ + tP * 8 + 0], q1 = S[ASQ + tP * 8 + 1];
    float q2 = S[ASQ + tP * 8 + 2], q3 = S[ASQ + tP * 8 + 3];
    float q4 = S[ASQ + tP * 8 + 4], q5 = S[ASQ + tP * 8 + 5];
    float q6 = S[ASQ + tP * 8 + 6];

    int s16 = tid >> 4, u = tid & 15, tg = u >> 2, dg = u & 3;  // GEMM mapping

    ull acc[8][4];
#pragma unroll
    for (int i = 0; i < 8; ++i)
#pragma unroll
        for (int jj = 0; jj < 4; ++jj) acc[i][jj] = 0ull;

    for (int ch = 0; ch < 8; ++ch) {
        int cbase = ch * 128;
        __syncthreads();   // prior GEMM reads done before overwrite

        if (tid < 128) {
            const float* xp = &xc[(b * NC + cbase + tid) * 3];
            float x0 = xp[0], x1 = xp[1], x2 = xp[2];
            S[AKV + tid] = x0;
            S[AKV + 128 + tid] = x1;
            S[AKV + 256 + tid] = x2;
            S[AKV + 384 + tid] = x0 * x0;
            S[AKV + 512 + tid] = x1 * x1;
            S[AKV + 640 + tid] = x2 * x2;
        }
        {
            const float4* ys = (const float4*)&yc[(b * NC + cbase) * 32];
            float4* yd = (float4*)&S[ASYC];
#pragma unroll
            for (int r = 0; r < 4; ++r) yd[tid + 256 * r] = ys[tid + 256 * r];
        }
        __syncthreads();

        // ---- logits (log2 units), paired over contexts ----
        float preg[16];
        float lmax = -1e30f;
        ull q0d = dup2(q0), q1d = dup2(q1), q2d = dup2(q2);
        ull q3d = dup2(q3), q4d = dup2(q4), q5d = dup2(q5);
        ull q6d = dup2(q6);
#pragma unroll
        for (int i4 = 0; i4 < 4; ++i4) {
            int c0 = cg * 16 + i4 * 4;
            ulonglong2 f0 = *(const ulonglong2*)&S[AKV + c0];
            ulonglong2 f1 = *(const ulonglong2*)&S[AKV + 128 + c0];
            ulonglong2 f2 = *(const ulonglong2*)&S[AKV + 256 + c0];
            ulonglong2 f3 = *(const ulonglong2*)&S[AKV + 384 + c0];
            ulonglong2 f4 = *(const ulonglong2*)&S[AKV + 512 + c0];
            ulonglong2 f5 = *(const ulonglong2*)&S[AKV + 640 + c0];
            ull P01 = q6d, P23 = q6d;
            fma2(P01, f0.x, q0d); fma2(P23, f0.y, q0d);
            fma2(P01, f1.x, q1d); fma2(P23, f1.y, q1d);
            fma2(P01, f2.x, q2d); fma2(P23, f2.y, q2d);
            fma2(P01, f3.x, q3d); fma2(P23, f3.y, q3d);
            fma2(P01, f4.x, q4d); fma2(P23, f4.y, q4d);
            fma2(P01, f5.x, q5d); fma2(P23, f5.y, q5d);
            unpack2(P01, preg[i4 * 4 + 0], preg[i4 * 4 + 1]);
            unpack2(P23, preg[i4 * 4 + 2], preg[i4 * 4 + 3]);
            lmax = fmaxf(lmax, fmaxf(fmaxf(preg[i4 * 4], preg[i4 * 4 + 1]),
                                     fmaxf(preg[i4 * 4 + 2], preg[i4 * 4 + 3])));
        }
        S[ARMX + cg * 32 + tP] = lmax;
        __syncthreads();

        if (tid < 32) {
            float m = S[ARMX + tid];
#pragma unroll
            for (int g2 = 1; g2 < 8; ++g2) m = fmaxf(m, S[ARMX + g2 * 32 + tid]);
            float mo = S[ASMX + tid], mn = fmaxf(mo, m);
            S[ASSC + tid] = ex2f(mo - mn);
            S[ASMX + tid] = mn;
        }
        __syncthreads();

        // rescale accumulators
#pragma unroll
        for (int wi = 0; wi < 8; ++wi) {
            ull scd = dup2(S[ASSC + tg * 8 + wi]);
#pragma unroll
            for (int dj = 0; dj < 4; ++dj) acc[wi][dj] = mul2(acc[wi][dj], scd);
        }

        // ---- weights + row sums ----
        {
            float m = S[ASMX + tP];
            float lsum = 0.f;
#pragma unroll
            for (int i = 0; i < 16; ++i) {
                float w = ex2f(preg[i] - m);
                lsum += w;
                S[ASW + (cg * 16 + i) * 36 + tP] = w;
            }
            S[ARSM + cg * 32 + tP] = lsum;
        }
        __syncthreads();

        if (tid < 32) {
            float sum = S[ARSM + tid];
#pragma unroll
            for (int g2 = 1; g2 < 8; ++g2) sum += S[ARSM + g2 * 32 + tid];
            S[ASL + tid] = fmaf(S[ASL + tid], S[ASSC + tid], sum);
        }

        // ---- value GEMM: acc[t][dpair] += w[c][t]*y[c][dpair] ----
#pragma unroll
        for (int k = 0; k < 8; ++k) {
            int c = s16 * 8 + k;
            float4 wa = *(const float4*)&S[ASW + c * 36 + tg * 8];
            float4 wb = *(const float4*)&S[ASW + c * 36 + tg * 8 + 4];
            ulonglong2 ya = *(const ulonglong2*)&S[ASYC + c * 32 + dg * 8];
            ulonglong2 yb = *(const ulonglong2*)&S[ASYC + c * 32 + dg * 8 + 4];
            ull w;
            w = dup2(wa.x);
            fma2(acc[0][0], ya.x, w); fma2(acc[0][1], ya.y, w);
            fma2(acc[0][2], yb.x, w); fma2(acc[0][3], yb.y, w);
            w = dup2(wa.y);
            fma2(acc[1][0], ya.x, w); fma2(acc[1][1], ya.y, w);
            fma2(acc[1][2], yb.x, w); fma2(acc[1][3], yb.y, w);
            w = dup2(wa.z);
            fma2(acc[2][0], ya.x, w); fma2(acc[2][1], ya.y, w);
            fma2(acc[2][2], yb.x, w); fma2(acc[2][3], yb.y, w);
            w = dup2(wa.w);
            fma2(acc[3][0], ya.x, w); fma2(acc[3][1], ya.y, w);
            fma2(acc[3][2], yb.x, w); fma2(acc[3][3], yb.y, w);
            w = dup2(wb.x);
            fma2(acc[4][0], ya.x, w); fma2(acc[4][1], ya.y, w);
            fma2(acc[4][2], yb.x, w); fma2(acc[4][3], yb.y, w);
            w = dup2(wb.y);
            fma2(acc[5][0], ya.x, w); fma2(acc[5][1], ya.y, w);
            fma2(acc[5][2], yb.x, w); fma2(acc[5][3], yb.y, w);
            w = dup2(wb.z);
            fma2(acc[6][0], ya.x, w); fma2(acc[6][1], ya.y, w);
            fma2(acc[6][2], yb.x, w); fma2(acc[6][3], yb.y, w);
            w = dup2(wb.w);
            fma2(acc[7][0], ya.x, w); fma2(acc[7][1], ya.y, w);
            fma2(acc[7][2], yb.x, w); fma2(acc[7][3], yb.y, w);
        }
    }
    __syncthreads();

    // ---- 16-way split reduction (two phases into 8 buffers) ----
    if (s16 < 8) {
#pragma unroll
        for (int wi = 0; wi < 8; ++wi) {
            int t = tg * 8 + wi;
            ulonglong2* dst = (ulonglong2*)&S[ARED + s16 * 1024 + t * 32 + dg * 8];
            ulonglong2 v0; v0.x = acc[wi][0]; v0.y = acc[wi][1];
            ulonglong2 v1; v1.x = acc[wi][2]; v1.y = acc[wi][3];
            dst[0] = v0; dst[1] = v1;
        }
    }
    __syncthreads();
    if (s16 >= 8) {
        int sI = s16 - 8;
#pragma unroll
        for (int wi = 0; wi < 8; ++wi) {
            int t = tg * 8 + wi;
            ulonglong2* p = (ulonglong2*)&S[ARED + sI * 1024 + t * 32 + dg * 8];
            ulonglong2 v0 = p[0], v1 = p[1];
            v0.x = add2(v0.x, acc[wi][0]); v0.y = add2(v0.y, acc[wi][1]);
            v1.x = add2(v1.x, acc[wi][2]); v1.y = add2(v1.y, acc[wi][3]);
            p[0] = v0; p[1] = v1;
        }
    }
    __syncthreads();

    {
        int t = tid >> 3, dq = tid & 7;
        ull r0 = 0ull, r1 = 0ull;
#pragma unroll
        for (int sI = 0; sI < 8; ++sI) {
            ulonglong2 v = *(const ulonglong2*)&S[ARED + sI * 1024 + t * 32 + dq * 4];
            r0 = add2(r0, v.x);
            r1 = add2(r1, v.y);
        }
        ull invd = dup2(1.0f / S[ASL + t]);
        r0 = mul2(r0, invd);
        r1 = mul2(r1, invd);
        ulonglong2 o; o.x = r0; o.y = r1;
        *(ulonglong2*)&out[(b * NT + t0 + t) * 32 + dq * 4] = o;
    }
}

// ============================== launch =====================================
extern "C" void kernel_launch(void* const* d_in, const int* in_sizes, int n_in,
                              void* d_out, int out_size) {
    (void)in_sizes; (void)n_in; (void)out_size;
    const float* xc = (const float*)d_in[0];
    const float* yc = (const float*)d_in[1];
    const float* xt = (const float*)d_in[2];
    const float* W0 = (const float*)d_in[3];
    const float* b0 = (const float*)d_in[4];
    const float* W1 = (const float*)d_in[5];
    const float* b1 = (const float*)d_in[6];
    const float* W2 = (const float*)d_in[7];
    const float* b2 = (const float*)d_in[8];
    const float* W3 = (const float*)d_in[9];
    const float* b3 = (const float*)d_in[10];
    float* out = (float*)d_out;

    size_t smem1 = SMEM1_FLOATS * sizeof(float);
    cudaFuncSetAttribute(mlp_kernel, cudaFuncAttributeMaxDynamicSharedMemorySize,
                         (int)smem1);

    mlp_kernel<<<256, TPB1, smem1>>>(xt, W0, b0, W1, b1, W2, b2, W3, b3);
    attn_kernel<<<dim3(NT / 32, B_SZ), 256>>>(xc, yc, out);
}